// round 9
// baseline (speedup 1.0000x reference)
#include <cuda_runtime.h>
#include <cuda_bf16.h>
#include <math.h>
#include <stdint.h>

// ---------------- problem constants ----------------
constexpr int kB   = 8;
constexpr int kT   = 1024;
constexpr int kC   = 768;
constexpr int kH   = 12;
constexpr int kDH  = 64;
constexpr int kHID = 1536;   // 2*C
constexpr int kM   = 16;
constexpr int kP   = 4;
constexpr int kPRE = kM + kP;      // 20
constexpr int kTA  = kT + kPRE;    // 1044
constexpr float kLR = 0.01f, kMU = 0.9f, kDECAY = 0.001f;

constexpr long OUT_N = (long)kB*kT*kC;
constexpr long W0_N  = (long)kB*kHID*kC;
constexpr long B0_N  = (long)kB*kHID;
constexpr long W1_N  = (long)kB*kC*kHID;
constexpr long B1_N  = (long)kB*kC;
constexpr long OFF_NW0  = OUT_N;
constexpr long OFF_NB0  = OFF_NW0  + W0_N;
constexpr long OFF_NW1  = OFF_NB0  + B0_N;
constexpr long OFF_NB1  = OFF_NW1  + W1_N;
constexpr long OFF_NMW0 = OFF_NB1  + B1_N;
constexpr long OFF_NMB0 = OFF_NMW0 + W0_N;
constexpr long OFF_NMW1 = OFF_NMB0 + B0_N;
constexpr long OFF_NMB1 = OFF_NMW1 + W1_N;

// ---------------- f32 scratch ----------------
__device__ float g_h    [(long)kB*kT*kHID];   // z (bw)
__device__ float g_hh   [(long)kB*kT*kHID];
__device__ float g_mem  [(long)kB*kT*kC];     // mem fwd / pred / dpred
__device__ float g_retr [(long)kB*kM*kC];
__device__ float g_xa   [(long)kB*kTA*kC];
__device__ float g_xa2  [(long)kB*kTA*kC];
__device__ float g_keys [(long)kB*kT*kC];
__device__ float g_vals [(long)kB*kT*kC];
__device__ float g_dh   [(long)kB*kT*kHID];
__device__ float g_gw0  [(long)kB*kHID*kC];
__device__ float g_gw1  [(long)kB*kC*kHID];
__device__ float g_gb0  [(long)kB*kHID];
__device__ float g_gb1  [(long)kB*kC];

// ---------------- bf16 split planes (size 2*N each: [hi | lo]) ----------------
constexpr long N_X     = (long)kB*kT*kC;
constexpr long N_Q     = N_X;
constexpr long N_H     = (long)kB*kT*kHID;
constexpr long N_POOL  = (long)kB*kM*kC;
constexpr long N_HLN   = (long)kB*kTA*kC;
constexpr long N_QKV   = (long)kB*kTA*3*kC;
constexpr long N_Y     = N_HLN;
constexpr long N_HFC   = (long)kB*kTA*4*kC;
constexpr long N_OUT   = N_X;
constexpr long N_KEYS  = N_X;
constexpr long N_HH    = N_H;
constexpr long N_DP    = N_X;
constexpr long N_DPT   = N_X;
constexpr long N_HHT   = N_H;
constexpr long N_DZT   = N_H;
constexpr long N_KEYST = N_X;
constexpr long N_W1T   = (long)kB*kHID*kC;
constexpr long N_SQW   = (long)kC*kC;
constexpr long N_ATTNW = (long)3*kC*kC;
constexpr long N_FCW   = (long)4*kC*kC;
constexpr long N_MLPW  = (long)4*kC*kC;
constexpr long N_W0    = (long)kB*kHID*kC;
constexpr long N_W1    = (long)kB*kC*kHID;

__device__ __nv_bfloat16 s_x    [2*N_X];
__device__ __nv_bfloat16 s_q    [2*N_Q];
__device__ __nv_bfloat16 s_h    [2*N_H];
__device__ __nv_bfloat16 s_pool [2*N_POOL];
__device__ __nv_bfloat16 s_hln  [2*N_HLN];
__device__ __nv_bfloat16 s_qkv  [2*N_QKV];
__device__ __nv_bfloat16 s_y    [2*N_Y];
__device__ __nv_bfloat16 s_hfc  [2*N_HFC];
__device__ __nv_bfloat16 s_out  [2*N_OUT];
__device__ __nv_bfloat16 s_keys [2*N_KEYS];
__device__ __nv_bfloat16 s_hh   [2*N_HH];
__device__ __nv_bfloat16 s_dp   [2*N_DP];
__device__ __nv_bfloat16 s_dpT  [2*N_DPT];
__device__ __nv_bfloat16 s_hhT  [2*N_HHT];
__device__ __nv_bfloat16 s_dzT  [2*N_DZT];
__device__ __nv_bfloat16 s_keysT[2*N_KEYST];
__device__ __nv_bfloat16 s_w1T  [2*N_W1T];
__device__ __nv_bfloat16 s_qw   [2*N_SQW];
__device__ __nv_bfloat16 s_kw   [2*N_SQW];
__device__ __nv_bfloat16 s_vw   [2*N_SQW];
__device__ __nv_bfloat16 s_ow   [2*N_SQW];
__device__ __nv_bfloat16 s_projw[2*N_SQW];
__device__ __nv_bfloat16 s_attnw[2*N_ATTNW];
__device__ __nv_bfloat16 s_fcw  [2*N_FCW];
__device__ __nv_bfloat16 s_mlpw [2*N_MLPW];
__device__ __nv_bfloat16 s_w0   [2*N_W0];
__device__ __nv_bfloat16 s_w1   [2*N_W1];

// ---------------- helpers ----------------
__device__ __forceinline__ uint32_t smem_u32(const void* p) {
    uint32_t a;
    asm("{ .reg .u64 t; cvta.to.shared.u64 t, %1; cvt.u32.u64 %0, t; }" : "=r"(a) : "l"(p));
    return a;
}

__device__ __forceinline__ void bsplit(float v, __nv_bfloat16& h, __nv_bfloat16& l) {
    h = __float2bfloat16(v);
    l = __float2bfloat16(v - __bfloat162float(h));
}

__device__ __forceinline__ uint32_t packb(__nv_bfloat16 a, __nv_bfloat16 b) {
    __nv_bfloat162 t; t.x = a; t.y = b;
    return *(uint32_t*)&t;
}

__device__ __forceinline__ void mma_bf16(float* d, const uint32_t* a, const uint32_t* b) {
    asm volatile(
        "mma.sync.aligned.m16n8k16.row.col.f32.bf16.bf16.f32 "
        "{%0,%1,%2,%3}, {%4,%5,%6,%7}, {%8,%9}, {%0,%1,%2,%3};"
        : "+f"(d[0]), "+f"(d[1]), "+f"(d[2]), "+f"(d[3])
        : "r"(a[0]), "r"(a[1]), "r"(a[2]), "r"(a[3]), "r"(b[0]), "r"(b[1]));
}

__device__ __forceinline__ void ldsm4(uint32_t* r, uint32_t addr) {
    asm volatile("ldmatrix.sync.aligned.m8n8.x4.shared.b16 {%0,%1,%2,%3}, [%4];"
        : "=r"(r[0]), "=r"(r[1]), "=r"(r[2]), "=r"(r[3]) : "r"(addr));
}

// ---------------- bf16-split GEMM (NT: A[M,K], B[N,K], K-major, pre-split hi/lo) ----------------
// Block 128x128, K-slab 32, 3-stage cp.async.
// Stage = 4 planes (Ahi,Alo,Bhi,Blo) x 128 rows x 32 bf16 (64B) = 32KB.
// Swizzle within a row: 16B chunk c stored at chunk (c ^ ((row>>1)&3)).
constexpr int MBM = 128, MBN = 128, MBK = 32, MSTG = 3;
constexpr int STG_WORDS = 8192;                    // 4 planes * 2048 words
constexpr unsigned MSMEM = MSTG * STG_WORDS * 4;   // 98304

enum { EP_NONE=0, EP_SILU=1, EP_GELU=2, EP_DSILU=3 };

template<int EPI, bool WF32, bool WSPLIT>
__global__ __launch_bounds__(256)
void bgemm_k(const __nv_bfloat16* __restrict__ A, const __nv_bfloat16* __restrict__ B,
             const float* __restrict__ bias, const float* __restrict__ res,
             float* __restrict__ C, __nv_bfloat16* __restrict__ Cs,
             int M, int N, int K,
             long aPlane, long bPlane, long cPlane,
             long sA, long sB, long sBias, long sRes, long sC)
{
    extern __shared__ float smf[];
    const uint32_t smb = smem_u32(smf);

    const int tid = threadIdx.x, lane = tid & 31, wid = tid >> 5;
    const int gid = lane >> 2, tg = lane & 3;
    const int wm = wid & 3, wn = wid >> 2;
    const int bz = blockIdx.z;
    const int m0 = blockIdx.y * MBM, n0 = blockIdx.x * MBN;
    const int nk = K / MBK;
    const int lq = lane >> 3, lsub = lane & 7;   // ldmatrix lane decomposition

    float acc[2][8][4];
#pragma unroll
    for (int i=0;i<2;i++)
#pragma unroll
        for (int j=0;j<8;j++)
#pragma unroll
            for (int r=0;r<4;r++) acc[i][j][r] = 0.f;

    auto load_stage = [&](int stage, int kt) {
        const int sw = stage * STG_WORDS;
#pragma unroll
        for (int it=0; it<8; it++) {
            int id = tid + it*256;
            int p = id >> 9;            // 0 Ahi, 1 Alo, 2 Bhi, 3 Blo
            int c = id & 511;
            int row = c >> 2, chunk = c & 3;
            const __nv_bfloat16* src;
            int sz = 16;
            if (p < 2) {
                int gm = m0 + row;
                int ok = gm < M;
                sz = ok ? 16 : 0;
                src = A + (p==1 ? aPlane : 0) + (long)bz*sA
                        + (long)(ok ? gm : 0)*K + kt*MBK + chunk*8;
            } else {
                src = B + (p==3 ? bPlane : 0) + (long)bz*sB
                        + (long)(n0 + row)*K + kt*MBK + chunk*8;
            }
            uint32_t dst = smb + (uint32_t)(sw + p*2048 + row*16
                              + ((chunk ^ ((row>>1)&3))*4))*4u;
            asm volatile("cp.async.cg.shared.global [%0], [%1], 16, %2;\n"
                         :: "r"(dst), "l"(src), "r"(sz));
        }
        asm volatile("cp.async.commit_group;\n");
    };

    auto compute = [&](int stage) {
        const uint32_t sbase = smb + (uint32_t)stage * STG_WORDS * 4u;
#pragma unroll
        for (int kh = 0; kh < 2; kh++) {
            uint32_t ahi[2][4], alo[2][4];
            // A: matrices (mlow,klow),(mhigh,klow),(mlow,khigh),(mhigh,khigh)
#pragma unroll
            for (int i=0;i<2;i++) {
                int row = wm*32 + i*16 + lsub + (lq & 1)*8;
                int chunk = 2*kh + (lq>>1);
                uint32_t off = (uint32_t)(row*64 + ((chunk ^ ((row>>1)&3)) << 4));
                ldsm4(ahi[i], sbase + off);
                ldsm4(alo[i], sbase + 8192u + off);
            }
#pragma unroll
            for (int jp=0;jp<4;jp++) {
                // B pair (j=2jp, 2jp+1): matrices (j,klow),(j,khigh),(j+1,klow),(j+1,khigh)
                int rowb = wn*64 + jp*16 + (lq>>1)*8 + lsub;
                int chunkb = 2*kh + (lq & 1);
                uint32_t offb = (uint32_t)(rowb*64 + ((chunkb ^ ((rowb>>1)&3)) << 4));
                uint32_t bh[4], bl[4];
                ldsm4(bh, sbase + 16384u + offb);
                ldsm4(bl, sbase + 24576u + offb);
                // term-major order: same-acc reuse distance = 4 (hides HMMA latency)
                mma_bf16(acc[0][2*jp],   alo[0], bh);
                mma_bf16(acc[0][2*jp+1], alo[0], bh+2);
                mma_bf16(acc[1][2*jp],   alo[1], bh);
                mma_bf16(acc[1][2*jp+1], alo[1], bh+2);
                mma_bf16(acc[0][2*jp],   ahi[0], bl);
                mma_bf16(acc[0][2*jp+1], ahi[0], bl+2);
                mma_bf16(acc[1][2*jp],   ahi[1], bl);
                mma_bf16(acc[1][2*jp+1], ahi[1], bl+2);
                mma_bf16(acc[0][2*jp],   ahi[0], bh);
                mma_bf16(acc[0][2*jp+1], ahi[0], bh+2);
                mma_bf16(acc[1][2*jp],   ahi[1], bh);
                mma_bf16(acc[1][2*jp+1], ahi[1], bh+2);
            }
        }
    };

    load_stage(0, 0);
    if (nk > 1) load_stage(1, 1);
    for (int kt = 0; kt < nk; kt++) {
        if (kt + 1 < nk) asm volatile("cp.async.wait_group 1;\n");
        else             asm volatile("cp.async.wait_group 0;\n");
        __syncthreads();
        compute(kt % MSTG);
        if (kt + 2 < nk) load_stage((kt + 2) % MSTG, kt + 2);
        __syncthreads();
    }

    const float* bp = bias ? bias + (long)bz*sBias : nullptr;
#pragma unroll
    for (int i=0;i<2;i++) {
#pragma unroll
        for (int half=0; half<2; half++) {
            int row = m0 + wm*32 + i*16 + gid + half*8;
            if (row >= M) continue;
            long rbase = (long)bz*sC + (long)row*N;
#pragma unroll
            for (int j=0;j<8;j++) {
                int col = n0 + wn*64 + j*8 + tg*2;
                float v0 = acc[i][j][half*2+0];
                float v1 = acc[i][j][half*2+1];
                if (bp) { v0 += bp[col]; v1 += bp[col+1]; }
                if (EPI == EP_SILU) {
                    v0 = v0 / (1.f + __expf(-v0));
                    v1 = v1 / (1.f + __expf(-v1));
                }
                if (EPI == EP_GELU) {
                    v0 = 0.5f*v0*(1.f + erff(v0*0.70710678118654752f));
                    v1 = 0.5f*v1*(1.f + erff(v1*0.70710678118654752f));
                }
                if (EPI == EP_DSILU) {
                    const float* zr = res + (long)bz*sRes + (long)row*N;
                    float z0 = zr[col], z1 = zr[col+1];
                    float s0 = 1.f/(1.f + __expf(-z0));
                    float s1 = 1.f/(1.f + __expf(-z1));
                    v0 *= s0*(1.f + z0*(1.f - s0));
                    v1 *= s1*(1.f + z1*(1.f - s1));
                }
                if (res && EPI != EP_DSILU) {
                    const float* rrow = res + (long)bz*sRes + (long)row*N;
                    v0 += rrow[col]; v1 += rrow[col+1];
                }
                if (WF32) {
                    float2 o; o.x = v0; o.y = v1;
                    *(float2*)(C + rbase + col) = o;
                }
                if (WSPLIT) {
                    __nv_bfloat16 h0,l0,h1,l1;
                    bsplit(v0, h0, l0); bsplit(v1, h1, l1);
                    *(__nv_bfloat162*)(Cs + rbase + col) = __nv_bfloat162{h0,h1};
                    *(__nv_bfloat162*)(Cs + cPlane + rbase + col) = __nv_bfloat162{l0,l1};
                }
            }
        }
    }
}

// ---------------- mma flash attention (split-bf16 qkv input) ----------------
__global__ __launch_bounds__(128)
void attn_mma_k(const __nv_bfloat16* __restrict__ qkvs, long qkvPlane,
                __nv_bfloat16* __restrict__ ys, long planeN)
{
    __shared__ __nv_bfloat16 Qh[64*72], Ql[64*72];
    __shared__ __nv_bfloat16 Kh[32*72], Kl[32*72];
    __shared__ __nv_bfloat16 Vh[64*40], Vl[64*40];

    const int bh = blockIdx.y;
    const int bb = bh / kH, hh = bh % kH;
    const int q0 = blockIdx.x * 64;
    const int tid = threadIdx.x, lane = tid & 31, wq = tid >> 5;
    const int gid = lane >> 2, tg = lane & 3;

    const __nv_bfloat16* qhiP = qkvs;
    const __nv_bfloat16* qloP = qkvs + qkvPlane;

    uint32_t* QwhW = (uint32_t*)Qh;  uint32_t* QwlW = (uint32_t*)Ql;
    uint32_t* KwhW = (uint32_t*)Kh;  uint32_t* KwlW = (uint32_t*)Kl;
    const uint32_t* Qwh = (const uint32_t*)Qh;
    const uint32_t* Qwl = (const uint32_t*)Ql;
    const uint32_t* Kwh = (const uint32_t*)Kh;
    const uint32_t* Kwl = (const uint32_t*)Kl;
    const uint32_t* Vwh = (const uint32_t*)Vh;
    const uint32_t* Vwl = (const uint32_t*)Vl;

    // ---- load Q tile (64 rows x 32 words) ----
#pragma unroll
    for (int it = 0; it < 16; it++) {
        int idx = tid + it*128;
        int row = idx >> 5, w = idx & 31;
        int qg = q0 + row;
        uint32_t vh = 0, vl = 0;
        if (qg < kTA) {
            long base = ((long)(bb*kTA + qg))*3*kC + hh*kDH + 2*w;
            vh = *(const uint32_t*)&qhiP[base];
            vl = *(const uint32_t*)&qloP[base];
        }
        QwhW[row*36 + w] = vh;
        QwlW[row*36 + w] = vl;
    }
    __syncthreads();

    // ---- Q fragments ----
    uint32_t qh[4][4], ql[4][4];
    {
        int r0 = wq*16 + gid;
#pragma unroll
        for (int c = 0; c < 4; c++) {
            qh[c][0] = Qwh[ r0    *36 + 8*c + tg];
            qh[c][1] = Qwh[(r0+8) *36 + 8*c + tg];
            qh[c][2] = Qwh[ r0    *36 + 8*c + tg + 4];
            qh[c][3] = Qwh[(r0+8) *36 + 8*c + tg + 4];
            ql[c][0] = Qwl[ r0    *36 + 8*c + tg];
            ql[c][1] = Qwl[(r0+8) *36 + 8*c + tg];
            ql[c][2] = Qwl[ r0    *36 + 8*c + tg + 4];
            ql[c][3] = Qwl[(r0+8) *36 + 8*c + tg + 4];
        }
    }

    float yacc[8][4];
#pragma unroll
    for (int f=0; f<8; f++)
#pragma unroll
        for (int e=0; e<4; e++) yacc[f][e] = 0.f;
    float mrow0 = -INFINITY, mrow1 = -INFINITY, lrow0 = 0.f, lrow1 = 0.f;

    const int qrow0 = q0 + wq*16 + gid;
    const int qrow1 = qrow0 + 8;

    int ntiles = (q0 == 0) ? (kTA + 31)/32 : (q0/32 + 2);
    if (ntiles > (kTA + 31)/32) ntiles = (kTA + 31)/32;

    for (int kt = 0; kt < ntiles; kt++) {
        __syncthreads();
        // ---- K tile (32 x 32 words) ----
#pragma unroll
        for (int it = 0; it < 8; it++) {
            int idx = tid + it*128;
            int row = idx >> 5, w = idx & 31;
            int kg = kt*32 + row;
            uint32_t vh = 0, vl = 0;
            if (kg < kTA) {
                long base = ((long)(bb*kTA + kg))*3*kC + kC + hh*kDH + 2*w;
                vh = *(const uint32_t*)&qhiP[base];
                vl = *(const uint32_t*)&qloP[base];
            }
            KwhW[row*36 + w] = vh;
            KwlW[row*36 + w] = vl;
        }
        // ---- V tile transposed ----
#pragma unroll
        for (int it = 0; it < 8; it++) {
            int idx = tid + it*128;
            int row = idx >> 5, w = idx & 31;
            int kg = kt*32 + row;
            uint32_t vh = 0, vl = 0;
            if (kg < kTA) {
                long base = ((long)(bb*kTA + kg))*3*kC + 2*kC + hh*kDH + 2*w;
                vh = *(const uint32_t*)&qhiP[base];
                vl = *(const uint32_t*)&qloP[base];
            }
            __nv_bfloat162 h2 = *(__nv_bfloat162*)&vh;
            __nv_bfloat162 l2 = *(__nv_bfloat162*)&vl;
            Vh[(2*w)*40 + row]   = h2.x;
            Vh[(2*w+1)*40 + row] = h2.y;
            Vl[(2*w)*40 + row]   = l2.x;
            Vl[(2*w+1)*40 + row] = l2.y;
        }
        __syncthreads();

        // ---- S = Q K^T ----
        float sfr[4][4];
#pragma unroll
        for (int j=0;j<4;j++)
#pragma unroll
            for (int e=0;e<4;e++) sfr[j][e] = 0.f;
#pragma unroll
        for (int j = 0; j < 4; j++) {
            int kr = 8*j + gid;
#pragma unroll
            for (int c = 0; c < 4; c++) {
                uint32_t kbh[2], kbl[2];
                kbh[0] = Kwh[kr*36 + 8*c + tg];
                kbh[1] = Kwh[kr*36 + 8*c + tg + 4];
                kbl[0] = Kwl[kr*36 + 8*c + tg];
                kbl[1] = Kwl[kr*36 + 8*c + tg + 4];
                mma_bf16(sfr[j], ql[c], kbh);
                mma_bf16(sfr[j], qh[c], kbl);
                mma_bf16(sfr[j], qh[c], kbh);
            }
        }

        // ---- scale + mask ----
#pragma unroll
        for (int j = 0; j < 4; j++) {
#pragma unroll
            for (int e = 0; e < 4; e++) {
                int qg = (e < 2) ? qrow0 : qrow1;
                int kg = kt*32 + 8*j + 2*tg + (e & 1);
                float s = sfr[j][e] * 0.125f;
                if (kg >= kTA || (qg >= kPRE && kg > qg)) s = -INFINITY;
                sfr[j][e] = s;
            }
        }

        // ---- online softmax ----
        float mx0 = -INFINITY, mx1 = -INFINITY;
#pragma unroll
        for (int j = 0; j < 4; j++) {
            mx0 = fmaxf(mx0, fmaxf(sfr[j][0], sfr[j][1]));
            mx1 = fmaxf(mx1, fmaxf(sfr[j][2], sfr[j][3]));
        }
        mx0 = fmaxf(mx0, __shfl_xor_sync(0xffffffffu, mx0, 1));
        mx0 = fmaxf(mx0, __shfl_xor_sync(0xffffffffu, mx0, 2));
        mx1 = fmaxf(mx1, __shfl_xor_sync(0xffffffffu, mx1, 1));
        mx1 = fmaxf(mx1, __shfl_xor_sync(0xffffffffu, mx1, 2));
        float mn0 = fmaxf(mrow0, mx0), mn1 = fmaxf(mrow1, mx1);
        float corr0 = __expf(mrow0 - mn0), corr1 = __expf(mrow1 - mn1);

        float sum0 = 0.f, sum1 = 0.f;
        uint32_t ph[2][4], pl[2][4];
#pragma unroll
        for (int kc = 0; kc < 2; kc++) {
            float p00,p01,p02,p03, p10,p11,p12,p13;
            {
                int j = 2*kc;
                p00 = __expf(sfr[j][0] - mn0); p01 = __expf(sfr[j][1] - mn0);
                p02 = __expf(sfr[j][2] - mn1); p03 = __expf(sfr[j][3] - mn1);
                j = 2*kc + 1;
                p10 = __expf(sfr[j][0] - mn0); p11 = __expf(sfr[j][1] - mn0);
                p12 = __expf(sfr[j][2] - mn1); p13 = __expf(sfr[j][3] - mn1);
            }
            sum0 += p00 + p01 + p10 + p11;
            sum1 += p02 + p03 + p12 + p13;
            __nv_bfloat16 h0,l0,h1,l1;
            bsplit(p00,h0,l0); bsplit(p01,h1,l1);
            ph[kc][0] = packb(h0,h1); pl[kc][0] = packb(l0,l1);
            bsplit(p02,h0,l0); bsplit(p03,h1,l1);
            ph[kc][1] = packb(h0,h1); pl[kc][1] = packb(l0,l1);
            bsplit(p10,h0,l0); bsplit(p11,h1,l1);
            ph[kc][2] = packb(h0,h1); pl[kc][2] = packb(l0,l1);
            bsplit(p12,h0,l0); bsplit(p13,h1,l1);
            ph[kc][3] = packb(h0,h1); pl[kc][3] = packb(l0,l1);
        }
        sum0 += __shfl_xor_sync(0xffffffffu, sum0, 1);
        sum0 += __shfl_xor_sync(0xffffffffu, sum0, 2);
        sum1 += __shfl_xor_sync(0xffffffffu, sum1, 1);
        sum1 += __shfl_xor_sync(0xffffffffu, sum1, 2);
        lrow0 = lrow0*corr0 + sum0;
        lrow1 = lrow1*corr1 + sum1;
#pragma unroll
        for (int f = 0; f < 8; f++) {
            yacc[f][0] *= corr0; yacc[f][1] *= corr0;
            yacc[f][2] *= corr1; yacc[f][3] *= corr1;
        }
        mrow0 = mn0; mrow1 = mn1;

        // ---- y += P V ----
#pragma unroll
        for (int f = 0; f < 8; f++) {
            int dr = 8*f + gid;
#pragma unroll
            for (int kc = 0; kc < 2; kc++) {
                uint32_t vbh[2], vbl[2];
                vbh[0] = Vwh[dr*20 + 8*kc + tg];
                vbh[1] = Vwh[dr*20 + 8*kc + tg + 4];
                vbl[0] = Vwl[dr*20 + 8*kc + tg];
                vbl[1] = Vwl[dr*20 + 8*kc + tg + 4];
                mma_bf16(yacc[f], pl[kc], vbh);
                mma_bf16(yacc[f], ph[kc], vbl);
                mma_bf16(yacc[f], ph[kc], vbh);
            }
        }
    }

    // ---- write y (split planes) ----
    float inv0 = 1.f / lrow0, inv1 = 1.f / lrow1;
#pragma unroll
    for (int f = 0; f < 8; f++) {
        int d = hh*kDH + 8*f + 2*tg;
        if (qrow0 < kTA) {
            long a = ((long)(bb*kTA + qrow0))*kC + d;
            __nv_bfloat16 h0,l0,h1,l1;
            bsplit(yacc[f][0]*inv0, h0, l0); bsplit(yacc[f][1]*inv0, h1, l1);
            *(__nv_bfloat162*)&ys[a] = __nv_bfloat162{h0,h1};
            *(__nv_bfloat162*)&ys[planeN + a] = __nv_bfloat162{l0,l1};
        }
        if (qrow1 < kTA) {
            long a = ((long)(bb*kTA + qrow1))*kC + d;
            __nv_bfloat16 h0,l0,h1,l1;
            bsplit(yacc[f][2]*inv1, h0, l0); bsplit(yacc[f][3]*inv1, h1, l1);
            *(__nv_bfloat162*)&ys[a] = __nv_bfloat162{h0,h1};
            *(__nv_bfloat162*)&ys[planeN + a] = __nv_bfloat162{l0,l1};
        }
    }
}

// ---------------- layernorm (writes split planes) ----------------
__global__ __launch_bounds__(256)
void ln_k(const float* __restrict__ x, const float* __restrict__ w,
          const float* __restrict__ b, __nv_bfloat16* __restrict__ o, long planeN)
{
    const long row = blockIdx.x;
    const float* xr = x + row*kC;
    float s = 0.f, s2 = 0.f;
    for (int c = threadIdx.x; c < kC; c += 256) { float v = xr[c]; s += v; s2 += v*v; }
    __shared__ float sh[64];
#pragma unroll
    for (int off=16;off;off>>=1){ s += __shfl_xor_sync(0xffffffffu,s,off); s2 += __shfl_xor_sync(0xffffffffu,s2,off); }
    int wid = threadIdx.x >> 5, lane = threadIdx.x & 31;
    if (lane == 0){ sh[wid] = s; sh[32+wid] = s2; }
    __syncthreads();
    if (threadIdx.x < 32) {
        s  = (lane < 8) ? sh[lane]    : 0.f;
        s2 = (lane < 8) ? sh[32+lane] : 0.f;
#pragma unroll
        for (int off=4;off;off>>=1){ s += __shfl_xor_sync(0xffffffffu,s,off); s2 += __shfl_xor_sync(0xffffffffu,s2,off); }
        if (lane == 0){ sh[0] = s; sh[1] = s2; }
    }
    __syncthreads();
    float mean = sh[0] * (1.f/kC);
    float var  = sh[1] * (1.f/kC) - mean*mean;
    float rstd = rsqrtf(var + 1e-5f);
    for (int c = threadIdx.x; c < kC; c += 256) {
        float v = (xr[c]-mean)*rstd*w[c] + b[c];
        __nv_bfloat16 h,lo2; bsplit(v,h,lo2);
        o[row*kC + c] = h;
        o[planeN + row*kC + c] = lo2;
    }
}

// ---------------- small kernels ----------------
__global__ void pool_k(const float* __restrict__ mem, __nv_bfloat16* __restrict__ pooled, long planeN)
{
    const int bm = blockIdx.x;
    const int bI = bm / kM, mI = bm % kM;
    const int seg = kT / kM;
    const float* src = mem + ((long)bI*kT + (long)mI*seg)*kC;
    for (int c = threadIdx.x; c < kC; c += blockDim.x) {
        float s = 0.f;
        for (int t = 0; t < seg; t++) s += src[(long)t*kC + c];
        float v = s * (1.f/seg);
        __nv_bfloat16 h,l; bsplit(v,h,l);
        pooled[(long)bm*kC + c] = h;
        pooled[planeN + (long)bm*kC + c] = l;
    }
}

__global__ void concat_k(const float* __restrict__ retr, const float* __restrict__ pm,
                         const float* __restrict__ x, float* __restrict__ xa)
{
    long i = (long)blockIdx.x*blockDim.x + threadIdx.x;
    if (i >= (long)kB*kTA*kC) return;
    int c = (int)(i % kC); long r = i / kC; int t = (int)(r % kTA); int b = (int)(r / kTA);
    float v;
    if (t < kM)        v = retr[((long)b*kM + t)*kC + c];
    else if (t < kPRE) v = pm[(long)(t-kM)*kC + c];
    else               v = x[((long)b*kT + (t-kPRE))*kC + c];
    xa[i] = v;
}

__global__ void copyout_k(const float* __restrict__ xa2, float* __restrict__ out,
                          __nv_bfloat16* __restrict__ outs, long planeN)
{
    long i = (long)blockIdx.x*blockDim.x + threadIdx.x;
    if (i >= OUT_N) return;
    int c = (int)(i % kC); long r = i / kC; int t = (int)(r % kT); int b = (int)(r / kT);
    float v = xa2[((long)b*kTA + kPRE + t)*kC + c];
    out[i] = v;
    __nv_bfloat16 h,l; bsplit(v,h,l);
    outs[i] = h; outs[planeN + i] = l;
}

__global__ void silu_k(const float* __restrict__ z, float* __restrict__ o,
                       __nv_bfloat16* __restrict__ os, long planeN, long n)
{
    long i = (long)blockIdx.x*blockDim.x + threadIdx.x;
    if (i >= n) return;
    float v = z[i];
    float r = v / (1.f + __expf(-v));
    o[i] = r;
    __nv_bfloat16 h,l; bsplit(r,h,l);
    os[i] = h; os[planeN + i] = l;
}

__global__ void dpred_k(float* __restrict__ p, const float* __restrict__ v,
                        __nv_bfloat16* __restrict__ ps, long planeN, long n, float scale)
{
    long i = (long)blockIdx.x*blockDim.x + threadIdx.x;
    if (i >= n) return;
    float r = (p[i] - v[i]) * scale;
    p[i] = r;
    __nv_bfloat16 h,l; bsplit(r,h,l);
    ps[i] = h; ps[planeN + i] = l;
}

__global__ void zero_k(float* __restrict__ a, long n)
{
    long i = (long)blockIdx.x*blockDim.x + threadIdx.x;
    if (i < n) a[i] = 0.f;
}

__global__ void colsum_k(const float* __restrict__ in, float* __restrict__ out,
                         int rows, int cols, int rowsPerSeg)
{
    int z = blockIdx.z;
    in  += (long)z*rows*cols;
    out += (long)z*cols;
    int j = blockIdx.x*blockDim.x + threadIdx.x;
    if (j >= cols) return;
    int t0 = blockIdx.y * rowsPerSeg;
    int t1 = t0 + rowsPerSeg; if (t1 > rows) t1 = rows;
    float s = 0.f;
    for (int t = t0; t < t1; t++) s += in[(long)t*cols + j];
    atomicAdd(out + j, s);
}

__global__ void update_k(const float* __restrict__ w, const float* __restrict__ mom,
                         const float* __restrict__ g, float* __restrict__ outW,
                         float* __restrict__ outM, long n)
{
    long i = (long)blockIdx.x*blockDim.x + threadIdx.x;
    if (i >= n) return;
    float nm = kMU*mom[i] + g[i];
    outM[i] = nm;
    outW[i] = (1.f - kDECAY)*w[i] - kLR*nm;
}

__global__ void split_k(const float* __restrict__ in, __nv_bfloat16* __restrict__ out, long n)
{
    long i = (long)blockIdx.x*blockDim.x + threadIdx.x;
    if (i >= n) return;
    __nv_bfloat16 h,l; bsplit(in[i],h,l);
    out[i] = h; out[n + i] = l;
}

__global__ void transpose_split_k(const float* __restrict__ in, __nv_bfloat16* __restrict__ out,
                                  long planeN, int rows, int cols)
{
    __shared__ float tile[32][33];
    long zoff = (long)blockIdx.z * rows * cols;
    int c0 = blockIdx.x*32, r0 = blockIdx.y*32;
    int tx = threadIdx.x, ty = threadIdx.y;
#pragma unroll
    for (int i = 0; i < 32; i += 8) {
        int r = r0 + ty + i, c = c0 + tx;
        if (r < rows && c < cols) tile[ty+i][tx] = in[zoff + (long)r*cols + c];
    }
    __syncthreads();
#pragma unroll
    for (int i = 0; i < 32; i += 8) {
        int r = c0 + ty + i, c = r0 + tx;
        if (r < cols && c < rows) {
            __nv_bfloat16 h,l; bsplit(tile[tx][ty+i],h,l);
            out[zoff + (long)r*rows + c] = h;
            out[planeN + zoff + (long)r*rows + c] = l;
        }
    }
}

// ---------------- host side ----------------
template<int EPI, bool WF32, bool WSPLIT>
static void bgemm(const __nv_bfloat16* A, long aPlane, long sA,
                  const __nv_bfloat16* B, long bPlane, long sB,
                  const float* bias, long sBias, const float* res, long sRes,
                  float* C, __nv_bfloat16* Cs, long cPlane, long sC,
                  int M, int N, int K, int batch)
{
    cudaFuncSetAttribute(bgemm_k<EPI,WF32,WSPLIT>,
                         cudaFuncAttributeMaxDynamicSharedMemorySize, MSMEM);
    dim3 grid(N/MBN, (M + MBM - 1)/MBM, batch);
    bgemm_k<EPI,WF32,WSPLIT><<<grid, 256, MSMEM>>>(A, B, bias, res, C, Cs,
        M, N, K, aPlane, bPlane, cPlane, sA, sB, sBias, sRes, sC);
}

static inline long cdiv(long a, long b){ return (a + b - 1)/b; }

#define GETF(var, sym) float* var; { void* _p=nullptr; cudaGetSymbolAddress(&_p, sym); var=(float*)_p; }
#define GETB(var, sym) __nv_bfloat16* var; { void* _p=nullptr; cudaGetSymbolAddress(&_p, sym); var=(__nv_bfloat16*)_p; }

extern "C" void kernel_launch(void* const* d_in, const int* in_sizes, int n_in,
                              void* d_out, int out_size)
{
    const float* x       = (const float*)d_in[0];
    const float* persist = (const float*)d_in[1];
    const float* ln1w    = (const float*)d_in[2];
    const float* ln1b    = (const float*)d_in[3];
    const float* ln2w    = (const float*)d_in[4];
    const float* ln2b    = (const float*)d_in[5];
    const float* attnw   = (const float*)d_in[6];
    const float* attnb   = (const float*)d_in[7];
    const float* projw   = (const float*)d_in[8];
    const float* projb   = (const float*)d_in[9];
    const float* fcw     = (const float*)d_in[10];
    const float* fcb     = (const float*)d_in[11];
    const float* mlpw    = (const float*)d_in[12];
    const float* mlpb    = (const float*)d_in[13];
    const float* qw      = (const float*)d_in[14];
    const float* qb      = (const float*)d_in[15];
    const float* kw      = (const float*)d_in[16];
    const float* kb      = (const float*)d_in[17];
    const float* vw      = (const float*)d_in[18];
    const float* vb      = (const float*)d_in[19];
    const float* ow      = (const float*)d_in[20];
    const float* ob      = (const float*)d_in[21];
    const float* memw0   = (const float*)d_in[22];
    const float* memb0   = (const float*)d_in[23];
    const float* memw1   = (const float*)d_in[24];
    const float* memb1   = (const float*)d_in[25];
    const float* momw0   = (const float*)d_in[26];
    const float* momb0   = (const float*)d_in[27];
    const float* momw1   = (const float*)d_in[28];
    const float* momb1   = (const float*)d_in[29];
    float* out = (float*)d_out;

    GETF(zbuf, g_h);    GETF(hh, g_hh);    GETF(memb, g_mem);  GETF(retr, g_retr);
    GETF(xa, g_xa);     GETF(xa2, g_xa2);  GETF(keys, g_keys);
    GETF(vals, g_vals); GETF(dh, g_dh);    GETF(gw0, g_gw0);   GETF(gw1, g_gw1);
    GETF(gb0, g_gb0);   GETF(gb1, g_gb1);

    GETB(px,    s_x);     GETB(pq,    s_q);     GETB(ph,    s_h);     GETB(ppool, s_pool);
    GETB(phln,  s_hln);   GETB(pqkv,  s_qkv);   GETB(py,    s_y);     GETB(phfc,  s_hfc);
    GETB(pout,  s_out);   GETB(pkeys, s_keys);  GETB(phh,   s_hh);    GETB(pdp,   s_dp);
    GETB(pdpT,  s_dpT);   GETB(phhT,  s_hhT);   GETB(pdzT,  s_dzT);   GETB(pkeysT,s_keysT);
    GETB(pw1T,  s_w1T);
    GETB(pqw,   s_qw);    GETB(pkw,   s_kw);    GETB(pvw,   s_vw);    GETB(pow_,  s_ow);
    GETB(pprojw,s_projw); GETB(pattnw,s_attnw); GETB(pfcw,  s_fcw);   GETB(pmlpw, s_mlpw);
    GETB(pw0,   s_w0);    GETB(pw1,   s_w1);

    const long sTC = (long)kT*kC, sTH = (long)kT*kHID;
    const long sW0 = (long)kHID*kC, sW1 = (long)kC*kHID;

    auto split = [&](const float* in, __nv_bfloat16* outp, long n){
        split_k<<<(unsigned)cdiv(n,256),256>>>(in, outp, n);
    };
    split(x, px, N_X);
    split(qw, pqw, N_SQW);   split(kw, pkw, N_SQW);   split(vw, pvw, N_SQW);
    split(ow, pow_, N_SQW);  split(projw, pprojw, N_SQW);
    split(attnw, pattnw, N_ATTNW);
    split(fcw, pfcw, N_FCW); split(mlpw, pmlpw, N_MLPW);
    split(memw0, pw0, N_W0); split(memw1, pw1, N_W1);
    transpose_split_k<<<dim3(kHID/32, kC/32, kB), dim3(32,8)>>>(memw1, pw1T, N_W1T, kC, kHID);

    // --- forward memory read path ---
    bgemm<EP_NONE,false,true>(px,N_X,0, pqw,N_SQW,0, qb,0, nullptr,0,
                              nullptr, pq,N_Q, 0, kB*kT, kC, kC, 1);
    bgemm<EP_SILU,false,true>(pq,N_Q,sTC, pw0,N_W0,sW0, memb0,kHID, nullptr,0,
                              nullptr, ph,N_H, sTH, kT, kHID, kC, kB);
    bgemm<EP_NONE,true,false>(ph,N_H,sTH, pw1,N_W1,sW1, memb1,kC, nullptr,0,
                              memb, nullptr,0, sTC, kT, kC, kHID, kB);
    pool_k<<<kB*kM, 256>>>(memb, ppool, N_POOL);
    bgemm<EP_NONE,true,false>(ppool,N_POOL,0, pow_,N_SQW,0, ob,0, nullptr,0,
                              retr, nullptr,0, 0, kB*kM, kC, kC, 1);
    {
        long n = (long)kB*kTA*kC;
        concat_k<<<(unsigned)cdiv(n,256),256>>>(retr, persist, x, xa);
    }

    // --- transformer block ---
    ln_k<<<kB*kTA,256>>>(xa, ln1w, ln1b, phln, N_HLN);
    bgemm<EP_NONE,false,true>(phln,N_HLN,0, pattnw,N_ATTNW,0, attnb,0, nullptr,0,
                              nullptr, pqkv,N_QKV, 0, kB*kTA, 3*kC, kC, 1);
    attn_mma_k<<<dim3((kTA+63)/64, kB*kH), 128>>>(pqkv, N_QKV, py, N_Y);
    bgemm<EP_NONE,true,false>(py,N_Y,0, pprojw,N_SQW,0, projb,0, xa,0,
                              xa2, nullptr,0, 0, kB*kTA, kC, kC, 1);
    ln_k<<<kB*kTA,256>>>(xa2, ln2w, ln2b, phln, N_HLN);
    bgemm<EP_GELU,false,true>(phln,N_HLN,0, pfcw,N_FCW,0, fcb,0, nullptr,0,
                              nullptr, phfc,N_HFC, 0, kB*kTA, 4*kC, kC, 1);
    bgemm<EP_NONE,true,false>(phfc,N_HFC,0, pmlpw,N_MLPW,0, mlpb,0, xa2,0,
                              xa2, nullptr,0, 0, kB*kTA, kC, 4*kC, 1);
    copyout_k<<<(unsigned)cdiv(OUT_N,256),256>>>(xa2, out, pout, N_OUT);

    // --- memory write path ---
    bgemm<EP_NONE,true,true>(pout,N_OUT,0, pkw,N_SQW,0, kb,0, nullptr,0,
                             keys, pkeys,N_KEYS, 0, kB*kT, kC, kC, 1);
    bgemm<EP_NONE,true,false>(pout,N_OUT,0, pvw,N_SQW,0, vb,0, nullptr,0,
                              vals, nullptr,0, 0, kB*kT, kC, kC, 1);
    bgemm<EP_NONE,true,false>(pkeys,N_KEYS,sTC, pw0,N_W0,sW0, memb0,kHID, nullptr,0,
                              zbuf, nullptr,0, sTH, kT, kHID, kC, kB);
    {
        long n = (long)kB*kT*kHID;
        silu_k<<<(unsigned)cdiv(n,256),256>>>(zbuf, hh, phh, N_HH, n);
    }
    bgemm<EP_NONE,true,false>(phh,N_HH,sTH, pw1,N_W1,sW1, memb1,kC, nullptr,0,
                              memb, nullptr,0, sTC, kT, kC, kHID, kB);
    {
        long n = (long)kB*kT*kC;
        dpred_k<<<(unsigned)cdiv(n,256),256>>>(memb, vals, pdp, N_DP, n, 2.f/((float)kT*(float)kC));
    }
    zero_k<<<(unsigned)cdiv(B0_N,256),256>>>(gb0, B0_N);
    zero_k<<<(unsigned)cdiv(B1_N,256),256>>>(gb1, B1_N);
    colsum_k<<<dim3((kC+255)/256, 8, kB),256>>>(memb, gb1, kT, kC, kT/8);

    transpose_split_k<<<dim3(kC/32,  kT/32, kB), dim3(32,8)>>>(memb, pdpT, N_DPT, kT, kC);
    transpose_split_k<<<dim3(kHID/32,kT/32, kB), dim3(32,8)>>>(hh,   phhT, N_HHT, kT, kHID);

    bgemm<EP_NONE,true,false>(pdpT,N_DPT,sTC, phhT,N_HHT,sTH, nullptr,0, nullptr,0,
                              gw1, nullptr,0, sW1, kC, kHID, kT, kB);
    // dh = dpred @ w1, fused with dsilu'(z)
    bgemm<EP_DSILU,true,false>(pdp,N_DP,sTC, pw1T,N_W1T,sW0, nullptr,0, zbuf,sTH,
                               dh, nullptr,0, sTH, kT, kHID, kC, kB);
    colsum_k<<<dim3((kHID+255)/256, 8, kB),256>>>(dh, gb0, kT, kHID, kT/8);
    transpose_split_k<<<dim3(kHID/32,kT/32, kB), dim3(32,8)>>>(dh,   pdzT,  N_DZT,  kT, kHID);
    transpose_split_k<<<dim3(kC/32,  kT/32, kB), dim3(32,8)>>>(keys, pkeysT,N_KEYST,kT, kC);
    bgemm<EP_NONE,true,false>(pdzT,N_DZT,sTH, pkeysT,N_KEYST,sTC, nullptr,0, nullptr,0,
                              gw0, nullptr,0, sW0, kHID, kC, kT, kB);

    // --- updates into output tuple ---
    update_k<<<(unsigned)cdiv(W0_N,256),256>>>(memw0, momw0, gw0, out+OFF_NW0, out+OFF_NMW0, W0_N);
    update_k<<<(unsigned)cdiv(B0_N,256),256>>>(memb0, momb0, gb0, out+OFF_NB0, out+OFF_NMB0, B0_N);
    update_k<<<(unsigned)cdiv(W1_N,256),256>>>(memw1, momw1, gw1, out+OFF_NW1, out+OFF_NMW1, W1_N);
    update_k<<<(unsigned)cdiv(B1_N,256),256>>>(memb1, momb1, gb1, out+OFF_NB1, out+OFF_NMB1, B1_N);

    (void)in_sizes; (void)n_in; (void)out_size;
}

// round 11
// speedup vs baseline: 1.0471x; 1.0471x over previous
#include <cuda_runtime.h>
#include <cuda_bf16.h>
#include <math.h>
#include <stdint.h>

// ---------------- problem constants ----------------
constexpr int kB   = 8;
constexpr int kT   = 1024;
constexpr int kC   = 768;
constexpr int kH   = 12;
constexpr int kDH  = 64;
constexpr int kHID = 1536;   // 2*C
constexpr int kM   = 16;
constexpr int kP   = 4;
constexpr int kPRE = kM + kP;      // 20
constexpr int kTA  = kT + kPRE;    // 1044
constexpr float kLR = 0.01f, kMU = 0.9f, kDECAY = 0.001f;

constexpr long OUT_N = (long)kB*kT*kC;
constexpr long W0_N  = (long)kB*kHID*kC;
constexpr long B0_N  = (long)kB*kHID;
constexpr long W1_N  = (long)kB*kC*kHID;
constexpr long B1_N  = (long)kB*kC;
constexpr long OFF_NW0  = OUT_N;
constexpr long OFF_NB0  = OFF_NW0  + W0_N;
constexpr long OFF_NW1  = OFF_NB0  + B0_N;
constexpr long OFF_NB1  = OFF_NW1  + W1_N;
constexpr long OFF_NMW0 = OFF_NB1  + B1_N;
constexpr long OFF_NMB0 = OFF_NMW0 + W0_N;
constexpr long OFF_NMW1 = OFF_NMB0 + B0_N;
constexpr long OFF_NMB1 = OFF_NMW1 + W1_N;

// ---------------- f32 scratch ----------------
__device__ float g_h    [(long)kB*kT*kHID];   // z (bw)
__device__ float g_hh   [(long)kB*kT*kHID];
__device__ float g_mem  [(long)kB*kT*kC];     // mem fwd / dpred
__device__ float g_retr [(long)kB*kM*kC];
__device__ float g_xa   [(long)kB*kTA*kC];
__device__ float g_xa2  [(long)kB*kTA*kC];
__device__ float g_keys [(long)kB*kT*kC];
__device__ float g_vals [(long)kB*kT*kC];
__device__ float g_dh   [(long)kB*kT*kHID];
__device__ float g_gw0  [(long)kB*kHID*kC];
__device__ float g_gw1  [(long)kB*kC*kHID];
__device__ float g_gb0  [(long)kB*kHID];
__device__ float g_gb1  [(long)kB*kC];

// ---------------- bf16 split planes (size 2*N each: [hi | lo]) ----------------
constexpr long N_X     = (long)kB*kT*kC;
constexpr long N_Q     = N_X;
constexpr long N_H     = (long)kB*kT*kHID;
constexpr long N_POOL  = (long)kB*kM*kC;
constexpr long N_HLN   = (long)kB*kTA*kC;
constexpr long N_QKV   = (long)kB*kTA*3*kC;
constexpr long N_Y     = N_HLN;
constexpr long N_HFC   = (long)kB*kTA*4*kC;
constexpr long N_OUT   = N_X;
constexpr long N_KEYS  = N_X;
constexpr long N_HH    = N_H;
constexpr long N_DP    = N_X;
constexpr long N_DPT   = N_X;
constexpr long N_HHT   = N_H;
constexpr long N_DZT   = N_H;
constexpr long N_KEYST = N_X;
constexpr long N_W1T   = (long)kB*kHID*kC;
constexpr long N_SQW   = (long)kC*kC;
constexpr long N_ATTNW = (long)3*kC*kC;
constexpr long N_FCW   = (long)4*kC*kC;
constexpr long N_MLPW  = (long)4*kC*kC;
constexpr long N_W0    = (long)kB*kHID*kC;
constexpr long N_W1    = (long)kB*kC*kHID;

__device__ __nv_bfloat16 s_x    [2*N_X];
__device__ __nv_bfloat16 s_q    [2*N_Q];
__device__ __nv_bfloat16 s_h    [2*N_H];
__device__ __nv_bfloat16 s_pool [2*N_POOL];
__device__ __nv_bfloat16 s_hln  [2*N_HLN];
__device__ __nv_bfloat16 s_qkv  [2*N_QKV];
__device__ __nv_bfloat16 s_y    [2*N_Y];
__device__ __nv_bfloat16 s_hfc  [2*N_HFC];
__device__ __nv_bfloat16 s_out  [2*N_OUT];
__device__ __nv_bfloat16 s_keys [2*N_KEYS];
__device__ __nv_bfloat16 s_hh   [2*N_HH];
__device__ __nv_bfloat16 s_dp   [2*N_DP];
__device__ __nv_bfloat16 s_dpT  [2*N_DPT];
__device__ __nv_bfloat16 s_hhT  [2*N_HHT];
__device__ __nv_bfloat16 s_dzT  [2*N_DZT];
__device__ __nv_bfloat16 s_keysT[2*N_KEYST];
__device__ __nv_bfloat16 s_w1T  [2*N_W1T];
__device__ __nv_bfloat16 s_qw   [2*N_SQW];
__device__ __nv_bfloat16 s_kw   [2*N_SQW];
__device__ __nv_bfloat16 s_vw   [2*N_SQW];
__device__ __nv_bfloat16 s_ow   [2*N_SQW];
__device__ __nv_bfloat16 s_projw[2*N_SQW];
__device__ __nv_bfloat16 s_attnw[2*N_ATTNW];
__device__ __nv_bfloat16 s_fcw  [2*N_FCW];
__device__ __nv_bfloat16 s_mlpw [2*N_MLPW];
__device__ __nv_bfloat16 s_w0   [2*N_W0];
__device__ __nv_bfloat16 s_w1   [2*N_W1];

// ---------------- helpers ----------------
__device__ __forceinline__ uint32_t smem_u32(const void* p) {
    uint32_t a;
    asm("{ .reg .u64 t; cvta.to.shared.u64 t, %1; cvt.u32.u64 %0, t; }" : "=r"(a) : "l"(p));
    return a;
}

__device__ __forceinline__ void bsplit(float v, __nv_bfloat16& h, __nv_bfloat16& l) {
    h = __float2bfloat16(v);
    l = __float2bfloat16(v - __bfloat162float(h));
}

__device__ __forceinline__ uint32_t packb(__nv_bfloat16 a, __nv_bfloat16 b) {
    __nv_bfloat162 t; t.x = a; t.y = b;
    return *(uint32_t*)&t;
}

__device__ __forceinline__ void mma_bf16(float* d, const uint32_t* a, const uint32_t* b) {
    asm volatile(
        "mma.sync.aligned.m16n8k16.row.col.f32.bf16.bf16.f32 "
        "{%0,%1,%2,%3}, {%4,%5,%6,%7}, {%8,%9}, {%0,%1,%2,%3};"
        : "+f"(d[0]), "+f"(d[1]), "+f"(d[2]), "+f"(d[3])
        : "r"(a[0]), "r"(a[1]), "r"(a[2]), "r"(a[3]), "r"(b[0]), "r"(b[1]));
}

__device__ __forceinline__ void ldsm4(uint32_t* r, uint32_t addr) {
    asm volatile("ldmatrix.sync.aligned.m8n8.x4.shared.b16 {%0,%1,%2,%3}, [%4];"
        : "=r"(r[0]), "=r"(r[1]), "=r"(r[2]), "=r"(r[3]) : "r"(addr));
}

// ---------------- bf16-split GEMM (NT, MBK=16, 48KB smem, 4 CTAs/SM) ----------------
constexpr int MBM = 128, MBN = 128, MBK = 16, MSTG = 3;
constexpr int STG_WORDS = 4096;                    // 4 planes * 1024 words
constexpr unsigned MSMEM = MSTG * STG_WORDS * 4;   // 49152

enum { EP_NONE=0, EP_SILU=1, EP_GELU=2, EP_DSILU=3, EP_SILUZ=4, EP_DPRED=5 };

template<int EPI, bool WF32, bool WSPLIT>
__global__ __launch_bounds__(256)
void bgemm_k(const __nv_bfloat16* __restrict__ A, const __nv_bfloat16* __restrict__ B,
             const float* __restrict__ bias, const float* __restrict__ res,
             float* __restrict__ C, __nv_bfloat16* __restrict__ Cs,
             float* __restrict__ C2, float scaleP,
             int M, int N, int K,
             long aPlane, long bPlane, long cPlane,
             long sA, long sB, long sBias, long sRes, long sC)
{
    extern __shared__ float smf[];
    const uint32_t smb = smem_u32(smf);

    const int tid = threadIdx.x, lane = tid & 31, wid = tid >> 5;
    const int gid = lane >> 2, tg = lane & 3;
    const int wm = wid & 3, wn = wid >> 2;
    const int bz = blockIdx.z;
    const int m0 = blockIdx.y * MBM, n0 = blockIdx.x * MBN;
    const int nk = K / MBK;
    const int lq = lane >> 3, lsub = lane & 7;

    float acc[2][8][4];
#pragma unroll
    for (int i=0;i<2;i++)
#pragma unroll
        for (int j=0;j<8;j++)
#pragma unroll
            for (int r=0;r<4;r++) acc[i][j][r] = 0.f;

    auto load_stage = [&](int stage, int kt) {
        const int sw = stage * STG_WORDS;
#pragma unroll
        for (int it=0; it<4; it++) {
            int id = tid + it*256;
            int p = id >> 8;            // 0 Ahi, 1 Alo, 2 Bhi, 3 Blo
            int c = id & 255;
            int row = c >> 1, half = c & 1;
            const __nv_bfloat16* src;
            int sz = 16;
            if (p < 2) {
                int gm = m0 + row;
                int ok = gm < M;
                sz = ok ? 16 : 0;
                src = A + (p==1 ? aPlane : 0) + (long)bz*sA
                        + (long)(ok ? gm : 0)*K + kt*MBK + half*8;
            } else {
                src = B + (p==3 ? bPlane : 0) + (long)bz*sB
                        + (long)(n0 + row)*K + kt*MBK + half*8;
            }
            uint32_t dst = smb + (uint32_t)(sw + p*1024 + row*8
                              + ((half*4) ^ (((row>>2)&1)<<2)))*4u;
            asm volatile("cp.async.cg.shared.global [%0], [%1], 16, %2;\n"
                         :: "r"(dst), "l"(src), "r"(sz));
        }
        asm volatile("cp.async.commit_group;\n");
    };

    auto compute = [&](int stage) {
        const uint32_t sbase = smb + (uint32_t)stage * STG_WORDS * 4u;
        uint32_t ahi[2][4], alo[2][4];
#pragma unroll
        for (int i=0;i<2;i++) {
            int row = wm*32 + i*16 + lsub + (lq & 1)*8;
            uint32_t off = (uint32_t)(row*32 + (((lq>>1)*16) ^ ((row & 4) << 2)));
            ldsm4(ahi[i], sbase + off);
            ldsm4(alo[i], sbase + 4096u + off);
        }
#pragma unroll
        for (int jp=0;jp<4;jp++) {
            int rowb = wn*64 + jp*16 + (lq>>1)*8 + lsub;
            uint32_t offb = (uint32_t)(rowb*32 + (((lq&1)*16) ^ ((rowb & 4) << 2)));
            uint32_t bh[4], bl[4];
            ldsm4(bh, sbase + 8192u  + offb);
            ldsm4(bl, sbase + 12288u + offb);
            // term-major order: same-acc reuse distance = 4
            mma_bf16(acc[0][2*jp],   alo[0], bh);
            mma_bf16(acc[0][2*jp+1], alo[0], bh+2);
            mma_bf16(acc[1][2*jp],   alo[1], bh);
            mma_bf16(acc[1][2*jp+1], alo[1], bh+2);
            mma_bf16(acc[0][2*jp],   ahi[0], bl);
            mma_bf16(acc[0][2*jp+1], ahi[0], bl+2);
            mma_bf16(acc[1][2*jp],   ahi[1], bl);
            mma_bf16(acc[1][2*jp+1], ahi[1], bl+2);
            mma_bf16(acc[0][2*jp],   ahi[0], bh);
            mma_bf16(acc[0][2*jp+1], ahi[0], bh+2);
            mma_bf16(acc[1][2*jp],   ahi[1], bh);
            mma_bf16(acc[1][2*jp+1], ahi[1], bh+2);
        }
    };

    load_stage(0, 0);
    if (nk > 1) load_stage(1, 1);
    for (int kt = 0; kt < nk; kt++) {
        if (kt + 1 < nk) asm volatile("cp.async.wait_group 1;\n");
        else             asm volatile("cp.async.wait_group 0;\n");
        __syncthreads();
        compute(kt % MSTG);
        if (kt + 2 < nk) load_stage((kt + 2) % MSTG, kt + 2);
        __syncthreads();
    }

    const float* bp = bias ? bias + (long)bz*sBias : nullptr;
#pragma unroll
    for (int i=0;i<2;i++) {
#pragma unroll
        for (int half=0; half<2; half++) {
            int row = m0 + wm*32 + i*16 + gid + half*8;
            if (row >= M) continue;
            long rbase = (long)bz*sC + (long)row*N;
#pragma unroll
            for (int j=0;j<8;j++) {
                int col = n0 + wn*64 + j*8 + tg*2;
                float v0 = acc[i][j][half*2+0];
                float v1 = acc[i][j][half*2+1];
                if (bp) { v0 += bp[col]; v1 += bp[col+1]; }
                float z0v = v0, z1v = v1;   // pre-activation (for EP_SILUZ)
                if (EPI == EP_SILU || EPI == EP_SILUZ) {
                    v0 = v0 / (1.f + __expf(-v0));
                    v1 = v1 / (1.f + __expf(-v1));
                }
                if (EPI == EP_GELU) {
                    v0 = 0.5f*v0*(1.f + erff(v0*0.70710678118654752f));
                    v1 = 0.5f*v1*(1.f + erff(v1*0.70710678118654752f));
                }
                if (EPI == EP_DSILU) {
                    const float* zr = res + (long)bz*sRes + (long)row*N;
                    float z0 = zr[col], z1 = zr[col+1];
                    float s0 = 1.f/(1.f + __expf(-z0));
                    float s1 = 1.f/(1.f + __expf(-z1));
                    v0 *= s0*(1.f + z0*(1.f - s0));
                    v1 *= s1*(1.f + z1*(1.f - s1));
                }
                if (EPI == EP_DPRED) {
                    const float* vr = res + (long)bz*sRes + (long)row*N;
                    v0 = (v0 - vr[col])   * scaleP;
                    v1 = (v1 - vr[col+1]) * scaleP;
                }
                if (EPI == EP_NONE && res) {
                    const float* rrow = res + (long)bz*sRes + (long)row*N;
                    v0 += rrow[col]; v1 += rrow[col+1];
                }
                if (WF32) {
                    float2 o;
                    if (EPI == EP_SILUZ) { o.x = z0v; o.y = z1v; }
                    else                 { o.x = v0;  o.y = v1;  }
                    *(float2*)(C + rbase + col) = o;
                }
                if (EPI == EP_SILUZ && C2) {
                    float2 o; o.x = v0; o.y = v1;
                    *(float2*)(C2 + rbase + col) = o;
                }
                if (WSPLIT) {
                    __nv_bfloat16 h0,l0,h1,l1;
                    bsplit(v0, h0, l0); bsplit(v1, h1, l1);
                    *(__nv_bfloat162*)(Cs + rbase + col) = __nv_bfloat162{h0,h1};
                    *(__nv_bfloat162*)(Cs + cPlane + rbase + col) = __nv_bfloat162{l0,l1};
                }
            }
        }
    }
}

// ---------------- mma flash attention (split-bf16 qkv input) ----------------
__global__ __launch_bounds__(128)
void attn_mma_k(const __nv_bfloat16* __restrict__ qkvs, long qkvPlane,
                __nv_bfloat16* __restrict__ ys, long planeN)
{
    __shared__ __nv_bfloat16 Qh[64*72], Ql[64*72];
    __shared__ __nv_bfloat16 Kh[32*72], Kl[32*72];
    __shared__ __nv_bfloat16 Vh[64*40], Vl[64*40];

    const int bh = blockIdx.y;
    const int bb = bh / kH, hh = bh % kH;
    const int q0 = blockIdx.x * 64;
    const int tid = threadIdx.x, lane = tid & 31, wq = tid >> 5;
    const int gid = lane >> 2, tg = lane & 3;

    const __nv_bfloat16* qhiP = qkvs;
    const __nv_bfloat16* qloP = qkvs + qkvPlane;

    uint32_t* QwhW = (uint32_t*)Qh;  uint32_t* QwlW = (uint32_t*)Ql;
    uint32_t* KwhW = (uint32_t*)Kh;  uint32_t* KwlW = (uint32_t*)Kl;
    const uint32_t* Qwh = (const uint32_t*)Qh;
    const uint32_t* Qwl = (const uint32_t*)Ql;
    const uint32_t* Kwh = (const uint32_t*)Kh;
    const uint32_t* Kwl = (const uint32_t*)Kl;
    const uint32_t* Vwh = (const uint32_t*)Vh;
    const uint32_t* Vwl = (const uint32_t*)Vl;

#pragma unroll
    for (int it = 0; it < 16; it++) {
        int idx = tid + it*128;
        int row = idx >> 5, w = idx & 31;
        int qg = q0 + row;
        uint32_t vh = 0, vl = 0;
        if (qg < kTA) {
            long base = ((long)(bb*kTA + qg))*3*kC + hh*kDH + 2*w;
            vh = *(const uint32_t*)&qhiP[base];
            vl = *(const uint32_t*)&qloP[base];
        }
        QwhW[row*36 + w] = vh;
        QwlW[row*36 + w] = vl;
    }
    __syncthreads();

    uint32_t qh[4][4], ql[4][4];
    {
        int r0 = wq*16 + gid;
#pragma unroll
        for (int c = 0; c < 4; c++) {
            qh[c][0] = Qwh[ r0    *36 + 8*c + tg];
            qh[c][1] = Qwh[(r0+8) *36 + 8*c + tg];
            qh[c][2] = Qwh[ r0    *36 + 8*c + tg + 4];
            qh[c][3] = Qwh[(r0+8) *36 + 8*c + tg + 4];
            ql[c][0] = Qwl[ r0    *36 + 8*c + tg];
            ql[c][1] = Qwl[(r0+8) *36 + 8*c + tg];
            ql[c][2] = Qwl[ r0    *36 + 8*c + tg + 4];
            ql[c][3] = Qwl[(r0+8) *36 + 8*c + tg + 4];
        }
    }

    float yacc[8][4];
#pragma unroll
    for (int f=0; f<8; f++)
#pragma unroll
        for (int e=0; e<4; e++) yacc[f][e] = 0.f;
    float mrow0 = -INFINITY, mrow1 = -INFINITY, lrow0 = 0.f, lrow1 = 0.f;

    const int qrow0 = q0 + wq*16 + gid;
    const int qrow1 = qrow0 + 8;

    int ntiles = (q0 == 0) ? (kTA + 31)/32 : (q0/32 + 2);
    if (ntiles > (kTA + 31)/32) ntiles = (kTA + 31)/32;

    for (int kt = 0; kt < ntiles; kt++) {
        __syncthreads();
#pragma unroll
        for (int it = 0; it < 8; it++) {
            int idx = tid + it*128;
            int row = idx >> 5, w = idx & 31;
            int kg = kt*32 + row;
            uint32_t vh = 0, vl = 0;
            if (kg < kTA) {
                long base = ((long)(bb*kTA + kg))*3*kC + kC + hh*kDH + 2*w;
                vh = *(const uint32_t*)&qhiP[base];
                vl = *(const uint32_t*)&qloP[base];
            }
            KwhW[row*36 + w] = vh;
            KwlW[row*36 + w] = vl;
        }
#pragma unroll
        for (int it = 0; it < 8; it++) {
            int idx = tid + it*128;
            int row = idx >> 5, w = idx & 31;
            int kg = kt*32 + row;
            uint32_t vh = 0, vl = 0;
            if (kg < kTA) {
                long base = ((long)(bb*kTA + kg))*3*kC + 2*kC + hh*kDH + 2*w;
                vh = *(const uint32_t*)&qhiP[base];
                vl = *(const uint32_t*)&qloP[base];
            }
            __nv_bfloat162 h2 = *(__nv_bfloat162*)&vh;
            __nv_bfloat162 l2 = *(__nv_bfloat162*)&vl;
            Vh[(2*w)*40 + row]   = h2.x;
            Vh[(2*w+1)*40 + row] = h2.y;
            Vl[(2*w)*40 + row]   = l2.x;
            Vl[(2*w+1)*40 + row] = l2.y;
        }
        __syncthreads();

        float sfr[4][4];
#pragma unroll
        for (int j=0;j<4;j++)
#pragma unroll
            for (int e=0;e<4;e++) sfr[j][e] = 0.f;
#pragma unroll
        for (int j = 0; j < 4; j++) {
            int kr = 8*j + gid;
#pragma unroll
            for (int c = 0; c < 4; c++) {
                uint32_t kbh[2], kbl[2];
                kbh[0] = Kwh[kr*36 + 8*c + tg];
                kbh[1] = Kwh[kr*36 + 8*c + tg + 4];
                kbl[0] = Kwl[kr*36 + 8*c + tg];
                kbl[1] = Kwl[kr*36 + 8*c + tg + 4];
                mma_bf16(sfr[j], ql[c], kbh);
                mma_bf16(sfr[j], qh[c], kbl);
                mma_bf16(sfr[j], qh[c], kbh);
            }
        }

#pragma unroll
        for (int j = 0; j < 4; j++) {
#pragma unroll
            for (int e = 0; e < 4; e++) {
                int qg = (e < 2) ? qrow0 : qrow1;
                int kg = kt*32 + 8*j + 2*tg + (e & 1);
                float s = sfr[j][e] * 0.125f;
                if (kg >= kTA || (qg >= kPRE && kg > qg)) s = -INFINITY;
                sfr[j][e] = s;
            }
        }

        float mx0 = -INFINITY, mx1 = -INFINITY;
#pragma unroll
        for (int j = 0; j < 4; j++) {
            mx0 = fmaxf(mx0, fmaxf(sfr[j][0], sfr[j][1]));
            mx1 = fmaxf(mx1, fmaxf(sfr[j][2], sfr[j][3]));
        }
        mx0 = fmaxf(mx0, __shfl_xor_sync(0xffffffffu, mx0, 1));
        mx0 = fmaxf(mx0, __shfl_xor_sync(0xffffffffu, mx0, 2));
        mx1 = fmaxf(mx1, __shfl_xor_sync(0xffffffffu, mx1, 1));
        mx1 = fmaxf(mx1, __shfl_xor_sync(0xffffffffu, mx1, 2));
        float mn0 = fmaxf(mrow0, mx0), mn1 = fmaxf(mrow1, mx1);
        float corr0 = __expf(mrow0 - mn0), corr1 = __expf(mrow1 - mn1);

        float sum0 = 0.f, sum1 = 0.f;
        uint32_t ph[2][4], pl[2][4];
#pragma unroll
        for (int kc = 0; kc < 2; kc++) {
            float p00,p01,p02,p03, p10,p11,p12,p13;
            {
                int j = 2*kc;
                p00 = __expf(sfr[j][0] - mn0); p01 = __expf(sfr[j][1] - mn0);
                p02 = __expf(sfr[j][2] - mn1); p03 = __expf(sfr[j][3] - mn1);
                j = 2*kc + 1;
                p10 = __expf(sfr[j][0] - mn0); p11 = __expf(sfr[j][1] - mn0);
                p12 = __expf(sfr[j][2] - mn1); p13 = __expf(sfr[j][3] - mn1);
            }
            sum0 += p00 + p01 + p10 + p11;
            sum1 += p02 + p03 + p12 + p13;
            __nv_bfloat16 h0,l0,h1,l1;
            bsplit(p00,h0,l0); bsplit(p01,h1,l1);
            ph[kc][0] = packb(h0,h1); pl[kc][0] = packb(l0,l1);
            bsplit(p02,h0,l0); bsplit(p03,h1,l1);
            ph[kc][1] = packb(h0,h1); pl[kc][1] = packb(l0,l1);
            bsplit(p10,h0,l0); bsplit(p11,h1,l1);
            ph[kc][2] = packb(h0,h1); pl[kc][2] = packb(l0,l1);
            bsplit(p12,h0,l0); bsplit(p13,h1,l1);
            ph[kc][3] = packb(h0,h1); pl[kc][3] = packb(l0,l1);
        }
        sum0 += __shfl_xor_sync(0xffffffffu, sum0, 1);
        sum0 += __shfl_xor_sync(0xffffffffu, sum0, 2);
        sum1 += __shfl_xor_sync(0xffffffffu, sum1, 1);
        sum1 += __shfl_xor_sync(0xffffffffu, sum1, 2);
        lrow0 = lrow0*corr0 + sum0;
        lrow1 = lrow1*corr1 + sum1;
#pragma unroll
        for (int f = 0; f < 8; f++) {
            yacc[f][0] *= corr0; yacc[f][1] *= corr0;
            yacc[f][2] *= corr1; yacc[f][3] *= corr1;
        }
        mrow0 = mn0; mrow1 = mn1;

#pragma unroll
        for (int f = 0; f < 8; f++) {
            int dr = 8*f + gid;
#pragma unroll
            for (int kc = 0; kc < 2; kc++) {
                uint32_t vbh[2], vbl[2];
                vbh[0] = Vwh[dr*20 + 8*kc + tg];
                vbh[1] = Vwh[dr*20 + 8*kc + tg + 4];
                vbl[0] = Vwl[dr*20 + 8*kc + tg];
                vbl[1] = Vwl[dr*20 + 8*kc + tg + 4];
                mma_bf16(yacc[f], pl[kc], vbh);
                mma_bf16(yacc[f], ph[kc], vbl);
                mma_bf16(yacc[f], ph[kc], vbh);
            }
        }
    }

    float inv0 = 1.f / lrow0, inv1 = 1.f / lrow1;
#pragma unroll
    for (int f = 0; f < 8; f++) {
        int d = hh*kDH + 8*f + 2*tg;
        if (qrow0 < kTA) {
            long a = ((long)(bb*kTA + qrow0))*kC + d;
            __nv_bfloat16 h0,l0,h1,l1;
            bsplit(yacc[f][0]*inv0, h0, l0); bsplit(yacc[f][1]*inv0, h1, l1);
            *(__nv_bfloat162*)&ys[a] = __nv_bfloat162{h0,h1};
            *(__nv_bfloat162*)&ys[planeN + a] = __nv_bfloat162{l0,l1};
        }
        if (qrow1 < kTA) {
            long a = ((long)(bb*kTA + qrow1))*kC + d;
            __nv_bfloat16 h0,l0,h1,l1;
            bsplit(yacc[f][2]*inv1, h0, l0); bsplit(yacc[f][3]*inv1, h1, l1);
            *(__nv_bfloat162*)&ys[a] = __nv_bfloat162{h0,h1};
            *(__nv_bfloat162*)&ys[planeN + a] = __nv_bfloat162{l0,l1};
        }
    }
}

// ---------------- layernorm (writes split planes) ----------------
__global__ __launch_bounds__(256)
void ln_k(const float* __restrict__ x, const float* __restrict__ w,
          const float* __restrict__ b, __nv_bfloat16* __restrict__ o, long planeN)
{
    const long row = blockIdx.x;
    const float* xr = x + row*kC;
    float s = 0.f, s2 = 0.f;
    for (int c = threadIdx.x; c < kC; c += 256) { float v = xr[c]; s += v; s2 += v*v; }
    __shared__ float sh[64];
#pragma unroll
    for (int off=16;off;off>>=1){ s += __shfl_xor_sync(0xffffffffu,s,off); s2 += __shfl_xor_sync(0xffffffffu,s2,off); }
    int wid = threadIdx.x >> 5, lane = threadIdx.x & 31;
    if (lane == 0){ sh[wid] = s; sh[32+wid] = s2; }
    __syncthreads();
    if (threadIdx.x < 32) {
        s  = (lane < 8) ? sh[lane]    : 0.f;
        s2 = (lane < 8) ? sh[32+lane] : 0.f;
#pragma unroll
        for (int off=4;off;off>>=1){ s += __shfl_xor_sync(0xffffffffu,s,off); s2 += __shfl_xor_sync(0xffffffffu,s2,off); }
        if (lane == 0){ sh[0] = s; sh[1] = s2; }
    }
    __syncthreads();
    float mean = sh[0] * (1.f/kC);
    float var  = sh[1] * (1.f/kC) - mean*mean;
    float rstd = rsqrtf(var + 1e-5f);
    for (int c = threadIdx.x; c < kC; c += 256) {
        float v = (xr[c]-mean)*rstd*w[c] + b[c];
        __nv_bfloat16 h,lo2; bsplit(v,h,lo2);
        o[row*kC + c] = h;
        o[planeN + row*kC + c] = lo2;
    }
}

// ---------------- small kernels ----------------
__global__ void pool_k(const float* __restrict__ mem, __nv_bfloat16* __restrict__ pooled, long planeN)
{
    const int bm = blockIdx.x;
    const int bI = bm / kM, mI = bm % kM;
    const int seg = kT / kM;
    const float* src = mem + ((long)bI*kT + (long)mI*seg)*kC;
    for (int c = threadIdx.x; c < kC; c += blockDim.x) {
        float s = 0.f;
        for (int t = 0; t < seg; t++) s += src[(long)t*kC + c];
        float v = s * (1.f/seg);
        __nv_bfloat16 h,l; bsplit(v,h,l);
        pooled[(long)bm*kC + c] = h;
        pooled[planeN + (long)bm*kC + c] = l;
    }
}

__global__ void concat_k(const float* __restrict__ retr, const float* __restrict__ pm,
                         const float* __restrict__ x, float* __restrict__ xa)
{
    long i = (long)blockIdx.x*blockDim.x + threadIdx.x;
    if (i >= (long)kB*kTA*kC) return;
    int c = (int)(i % kC); long r = i / kC; int t = (int)(r % kTA); int b = (int)(r / kTA);
    float v;
    if (t < kM)        v = retr[((long)b*kM + t)*kC + c];
    else if (t < kPRE) v = pm[(long)(t-kM)*kC + c];
    else               v = x[((long)b*kT + (t-kPRE))*kC + c];
    xa[i] = v;
}

__global__ void copyout_k(const float* __restrict__ xa2, float* __restrict__ out,
                          __nv_bfloat16* __restrict__ outs, long planeN)
{
    long i = (long)blockIdx.x*blockDim.x + threadIdx.x;
    if (i >= OUT_N) return;
    int c = (int)(i % kC); long r = i / kC; int t = (int)(r % kT); int b = (int)(r / kT);
    float v = xa2[((long)b*kTA + kPRE + t)*kC + c];
    out[i] = v;
    __nv_bfloat16 h,l; bsplit(v,h,l);
    outs[i] = h; outs[planeN + i] = l;
}

__global__ void zero_k(float* __restrict__ a, long n)
{
    long i = (long)blockIdx.x*blockDim.x + threadIdx.x;
    if (i < n) a[i] = 0.f;
}

__global__ void colsum_k(const float* __restrict__ in, float* __restrict__ out,
                         int rows, int cols, int rowsPerSeg)
{
    int z = blockIdx.z;
    in  += (long)z*rows*cols;
    out += (long)z*cols;
    int j = blockIdx.x*blockDim.x + threadIdx.x;
    if (j >= cols) return;
    int t0 = blockIdx.y * rowsPerSeg;
    int t1 = t0 + rowsPerSeg; if (t1 > rows) t1 = rows;
    float s = 0.f;
    for (int t = t0; t < t1; t++) s += in[(long)t*cols + j];
    atomicAdd(out + j, s);
}

__global__ void update_k(const float* __restrict__ w, const float* __restrict__ mom,
                         const float* __restrict__ g, float* __restrict__ outW,
                         float* __restrict__ outM, long n)
{
    long i = (long)blockIdx.x*blockDim.x + threadIdx.x;
    if (i >= n) return;
    float nm = kMU*mom[i] + g[i];
    outM[i] = nm;
    outW[i] = (1.f - kDECAY)*w[i] - kLR*nm;
}

__global__ void split_k(const float* __restrict__ in, __nv_bfloat16* __restrict__ out, long n)
{
    long i = (long)blockIdx.x*blockDim.x + threadIdx.x;
    if (i >= n) return;
    __nv_bfloat16 h,l; bsplit(in[i],h,l);
    out[i] = h; out[n + i] = l;
}

__global__ void transpose_split_k(const float* __restrict__ in, __nv_bfloat16* __restrict__ out,
                                  long planeN, int rows, int cols)
{
    __shared__ float tile[32][33];
    long zoff = (long)blockIdx.z * rows * cols;
    int c0 = blockIdx.x*32, r0 = blockIdx.y*32;
    int tx = threadIdx.x, ty = threadIdx.y;
#pragma unroll
    for (int i = 0; i < 32; i += 8) {
        int r = r0 + ty + i, c = c0 + tx;
        if (r < rows && c < cols) tile[ty+i][tx] = in[zoff + (long)r*cols + c];
    }
    __syncthreads();
#pragma unroll
    for (int i = 0; i < 32; i += 8) {
        int r = c0 + ty + i, c = r0 + tx;
        if (r < cols && c < rows) {
            __nv_bfloat16 h,l; bsplit(tile[tx][ty+i],h,l);
            out[zoff + (long)r*rows + c] = h;
            out[planeN + zoff + (long)r*rows + c] = l;
        }
    }
}

// ---------------- host side ----------------
template<int EPI, bool WF32, bool WSPLIT>
static void bgemm(const __nv_bfloat16* A, long aPlane, long sA,
                  const __nv_bfloat16* B, long bPlane, long sB,
                  const float* bias, long sBias, const float* res, long sRes,
                  float* C, __nv_bfloat16* Cs, long cPlane, long sC,
                  int M, int N, int K, int batch,
                  float* C2 = nullptr, float scaleP = 0.f)
{
    cudaFuncSetAttribute(bgemm_k<EPI,WF32,WSPLIT>,
                         cudaFuncAttributeMaxDynamicSharedMemorySize, MSMEM);
    dim3 grid(N/MBN, (M + MBM - 1)/MBM, batch);
    bgemm_k<EPI,WF32,WSPLIT><<<grid, 256, MSMEM>>>(A, B, bias, res, C, Cs, C2, scaleP,
        M, N, K, aPlane, bPlane, cPlane, sA, sB, sBias, sRes, sC);
}

static inline long cdiv(long a, long b){ return (a + b - 1)/b; }

#define GETF(var, sym) float* var; { void* _p=nullptr; cudaGetSymbolAddress(&_p, sym); var=(float*)_p; }
#define GETB(var, sym) __nv_bfloat16* var; { void* _p=nullptr; cudaGetSymbolAddress(&_p, sym); var=(__nv_bfloat16*)_p; }

extern "C" void kernel_launch(void* const* d_in, const int* in_sizes, int n_in,
                              void* d_out, int out_size)
{
    const float* x       = (const float*)d_in[0];
    const float* persist = (const float*)d_in[1];
    const float* ln1w    = (const float*)d_in[2];
    const float* ln1b    = (const float*)d_in[3];
    const float* ln2w    = (const float*)d_in[4];
    const float* ln2b    = (const float*)d_in[5];
    const float* attnw   = (const float*)d_in[6];
    const float* attnb   = (const float*)d_in[7];
    const float* projw   = (const float*)d_in[8];
    const float* projb   = (const float*)d_in[9];
    const float* fcw     = (const float*)d_in[10];
    const float* fcb     = (const float*)d_in[11];
    const float* mlpw    = (const float*)d_in[12];
    const float* mlpb    = (const float*)d_in[13];
    const float* qw      = (const float*)d_in[14];
    const float* qb      = (const float*)d_in[15];
    const float* kw      = (const float*)d_in[16];
    const float* kb      = (const float*)d_in[17];
    const float* vw      = (const float*)d_in[18];
    const float* vb      = (const float*)d_in[19];
    const float* ow      = (const float*)d_in[20];
    const float* ob      = (const float*)d_in[21];
    const float* memw0   = (const float*)d_in[22];
    const float* memb0   = (const float*)d_in[23];
    const float* memw1   = (const float*)d_in[24];
    const float* memb1   = (const float*)d_in[25];
    const float* momw0   = (const float*)d_in[26];
    const float* momb0   = (const float*)d_in[27];
    const float* momw1   = (const float*)d_in[28];
    const float* momb1   = (const float*)d_in[29];
    float* out = (float*)d_out;

    GETF(zbuf, g_h);    GETF(hh, g_hh);    GETF(memb, g_mem);  GETF(retr, g_retr);
    GETF(xa, g_xa);     GETF(xa2, g_xa2);  GETF(keys, g_keys);
    GETF(vals, g_vals); GETF(dh, g_dh);    GETF(gw0, g_gw0);   GETF(gw1, g_gw1);
    GETF(gb0, g_gb0);   GETF(gb1, g_gb1);

    GETB(px,    s_x);     GETB(pq,    s_q);     GETB(ph,    s_h);     GETB(ppool, s_pool);
    GETB(phln,  s_hln);   GETB(pqkv,  s_qkv);   GETB(py,    s_y);     GETB(phfc,  s_hfc);
    GETB(pout,  s_out);   GETB(pkeys, s_keys);  GETB(phh,   s_hh);    GETB(pdp,   s_dp);
    GETB(pdpT,  s_dpT);   GETB(phhT,  s_hhT);   GETB(pdzT,  s_dzT);   GETB(pkeysT,s_keysT);
    GETB(pw1T,  s_w1T);
    GETB(pqw,   s_qw);    GETB(pkw,   s_kw);    GETB(pvw,   s_vw);    GETB(pow_,  s_ow);
    GETB(pprojw,s_projw); GETB(pattnw,s_attnw); GETB(pfcw,  s_fcw);   GETB(pmlpw, s_mlpw);
    GETB(pw0,   s_w0);    GETB(pw1,   s_w1);

    const long sTC = (long)kT*kC, sTH = (long)kT*kHID;
    const long sW0 = (long)kHID*kC, sW1 = (long)kC*kHID;

    auto split = [&](const float* in, __nv_bfloat16* outp, long n){
        split_k<<<(unsigned)cdiv(n,256),256>>>(in, outp, n);
    };
    split(x, px, N_X);
    split(qw, pqw, N_SQW);   split(kw, pkw, N_SQW);   split(vw, pvw, N_SQW);
    split(ow, pow_, N_SQW);  split(projw, pprojw, N_SQW);
    split(attnw, pattnw, N_ATTNW);
    split(fcw, pfcw, N_FCW); split(mlpw, pmlpw, N_MLPW);
    split(memw0, pw0, N_W0); split(memw1, pw1, N_W1);
    transpose_split_k<<<dim3(kHID/32, kC/32, kB), dim3(32,8)>>>(memw1, pw1T, N_W1T, kC, kHID);

    // --- forward memory read path ---
    bgemm<EP_NONE,false,true>(px,N_X,0, pqw,N_SQW,0, qb,0, nullptr,0,
                              nullptr, pq,N_Q, 0, kB*kT, kC, kC, 1);
    bgemm<EP_SILU,false,true>(pq,N_Q,sTC, pw0,N_W0,sW0, memb0,kHID, nullptr,0,
                              nullptr, ph,N_H, sTH, kT, kHID, kC, kB);
    bgemm<EP_NONE,true,false>(ph,N_H,sTH, pw1,N_W1,sW1, memb1,kC, nullptr,0,
                              memb, nullptr,0, sTC, kT, kC, kHID, kB);
    pool_k<<<kB*kM, 256>>>(memb, ppool, N_POOL);
    bgemm<EP_NONE,true,false>(ppool,N_POOL,0, pow_,N_SQW,0, ob,0, nullptr,0,
                              retr, nullptr,0, 0, kB*kM, kC, kC, 1);
    {
        long n = (long)kB*kTA*kC;
        concat_k<<<(unsigned)cdiv(n,256),256>>>(retr, persist, x, xa);
    }

    // --- transformer block ---
    ln_k<<<kB*kTA,256>>>(xa, ln1w, ln1b, phln, N_HLN);
    bgemm<EP_NONE,false,true>(phln,N_HLN,0, pattnw,N_ATTNW,0, attnb,0, nullptr,0,
                              nullptr, pqkv,N_QKV, 0, kB*kTA, 3*kC, kC, 1);
    attn_mma_k<<<dim3((kTA+63)/64, kB*kH), 128>>>(pqkv, N_QKV, py, N_Y);
    bgemm<EP_NONE,true,false>(py,N_Y,0, pprojw,N_SQW,0, projb,0, xa,0,
                              xa2, nullptr,0, 0, kB*kTA, kC, kC, 1);
    ln_k<<<kB*kTA,256>>>(xa2, ln2w, ln2b, phln, N_HLN);
    bgemm<EP_GELU,false,true>(phln,N_HLN,0, pfcw,N_FCW,0, fcb,0, nullptr,0,
                              nullptr, phfc,N_HFC, 0, kB*kTA, 4*kC, kC, 1);
    bgemm<EP_NONE,true,false>(phfc,N_HFC,0, pmlpw,N_MLPW,0, mlpb,0, xa2,0,
                              xa2, nullptr,0, 0, kB*kTA, kC, 4*kC, 1);
    copyout_k<<<(unsigned)cdiv(OUT_N,256),256>>>(xa2, out, pout, N_OUT);

    // --- memory write path ---
    bgemm<EP_NONE,true,true>(pout,N_OUT,0, pkw,N_SQW,0, kb,0, nullptr,0,
                             keys, pkeys,N_KEYS, 0, kB*kT, kC, kC, 1);
    bgemm<EP_NONE,true,false>(pout,N_OUT,0, pvw,N_SQW,0, vb,0, nullptr,0,
                              vals, nullptr,0, 0, kB*kT, kC, kC, 1);
    // z = keys@w0^T + b0 ; fused: writes z (f32), silu(z) (f32 -> hh), silu(z) split -> phh
    bgemm<EP_SILUZ,true,true>(pkeys,N_KEYS,sTC, pw0,N_W0,sW0, memb0,kHID, nullptr,0,
                              zbuf, phh,N_HH, sTH, kT, kHID, kC, kB, hh);
    // dpred = (hh@w1^T + b1 - vals) * scale ; fused: writes f32 -> memb, split -> pdp
    bgemm<EP_DPRED,true,true>(phh,N_HH,sTH, pw1,N_W1,sW1, memb1,kC, vals,sTC,
                              memb, pdp,N_DP, sTC, kT, kC, kHID, kB,
                              nullptr, 2.f/((float)kT*(float)kC));
    zero_k<<<(unsigned)cdiv(B0_N,256),256>>>(gb0, B0_N);
    zero_k<<<(unsigned)cdiv(B1_N,256),256>>>(gb1, B1_N);
    colsum_k<<<dim3((kC+255)/256, 8, kB),256>>>(memb, gb1, kT, kC, kT/8);

    transpose_split_k<<<dim3(kC/32,  kT/32, kB), dim3(32,8)>>>(memb, pdpT, N_DPT, kT, kC);
    transpose_split_k<<<dim3(kHID/32,kT/32, kB), dim3(32,8)>>>(hh,   phhT, N_HHT, kT, kHID);

    bgemm<EP_NONE,true,false>(pdpT,N_DPT,sTC, phhT,N_HHT,sTH, nullptr,0, nullptr,0,
                              gw1, nullptr,0, sW1, kC, kHID, kT, kB);
    // dh = dpred @ w1, fused with dsilu'(z)
    bgemm<EP_DSILU,true,false>(pdp,N_DP,sTC, pw1T,N_W1T,sW0, nullptr,0, zbuf,sTH,
                               dh, nullptr,0, sTH, kT, kHID, kC, kB);
    colsum_k<<<dim3((kHID+255)/256, 8, kB),256>>>(dh, gb0, kT, kHID, kT/8);
    transpose_split_k<<<dim3(kHID/32,kT/32, kB), dim3(32,8)>>>(dh,   pdzT,  N_DZT,  kT, kHID);
    transpose_split_k<<<dim3(kC/32,  kT/32, kB), dim3(32,8)>>>(keys, pkeysT,N_KEYST,kT, kC);
    bgemm<EP_NONE,true,false>(pdzT,N_DZT,sTH, pkeysT,N_KEYST,sTC, nullptr,0, nullptr,0,
                              gw0, nullptr,0, sW0, kHID, kC, kT, kB);

    // --- updates into output tuple ---
    update_k<<<(unsigned)cdiv(W0_N,256),256>>>(memw0, momw0, gw0, out+OFF_NW0, out+OFF_NMW0, W0_N);
    update_k<<<(unsigned)cdiv(B0_N,256),256>>>(memb0, momb0, gb0, out+OFF_NB0, out+OFF_NMB0, B0_N);
    update_k<<<(unsigned)cdiv(W1_N,256),256>>>(memw1, momw1, gw1, out+OFF_NW1, out+OFF_NMW1, W1_N);
    update_k<<<(unsigned)cdiv(B1_N,256),256>>>(memb1, momb1, gb1, out+OFF_NB1, out+OFF_NMB1, B1_N);

    (void)in_sizes; (void)n_in; (void)out_size;
}

// round 12
// speedup vs baseline: 1.0680x; 1.0200x over previous
#include <cuda_runtime.h>
#include <cuda_bf16.h>
#include <math.h>
#include <stdint.h>

// ---------------- problem constants ----------------
constexpr int kB   = 8;
constexpr int kT   = 1024;
constexpr int kC   = 768;
constexpr int kH   = 12;
constexpr int kDH  = 64;
constexpr int kHID = 1536;   // 2*C
constexpr int kM   = 16;
constexpr int kP   = 4;
constexpr int kPRE = kM + kP;      // 20
constexpr int kTA  = kT + kPRE;    // 1044
constexpr float kLR = 0.01f, kMU = 0.9f, kDECAY = 0.001f;

constexpr long OUT_N = (long)kB*kT*kC;
constexpr long W0_N  = (long)kB*kHID*kC;
constexpr long B0_N  = (long)kB*kHID;
constexpr long W1_N  = (long)kB*kC*kHID;
constexpr long B1_N  = (long)kB*kC;
constexpr long OFF_NW0  = OUT_N;
constexpr long OFF_NB0  = OFF_NW0  + W0_N;
constexpr long OFF_NW1  = OFF_NB0  + B0_N;
constexpr long OFF_NB1  = OFF_NW1  + W1_N;
constexpr long OFF_NMW0 = OFF_NB1  + B1_N;
constexpr long OFF_NMB0 = OFF_NMW0 + W0_N;
constexpr long OFF_NMW1 = OFF_NMB0 + B0_N;
constexpr long OFF_NMB1 = OFF_NMW1 + W1_N;

// ---------------- f32 scratch ----------------
__device__ float g_h    [(long)kB*kT*kHID];   // z (bw)
__device__ float g_hh   [(long)kB*kT*kHID];
__device__ float g_mem  [(long)kB*kT*kC];     // mem fwd / dpred
__device__ float g_retr [(long)kB*kM*kC];
__device__ float g_xa   [(long)kB*kTA*kC];
__device__ float g_xa2  [(long)kB*kTA*kC];
__device__ float g_keys [(long)kB*kT*kC];
__device__ float g_vals [(long)kB*kT*kC];
__device__ float g_dh   [(long)kB*kT*kHID];
__device__ float g_gw0  [(long)kB*kHID*kC];
__device__ float g_gw1  [(long)kB*kC*kHID];
__device__ float g_gb0  [(long)kB*kHID];
__device__ float g_gb1  [(long)kB*kC];

// ---------------- bf16 split planes (size 2*N each: [hi | lo]) ----------------
constexpr long N_X     = (long)kB*kT*kC;
constexpr long N_Q     = N_X;
constexpr long N_H     = (long)kB*kT*kHID;
constexpr long N_POOL  = (long)kB*kM*kC;
constexpr long N_HLN   = (long)kB*kTA*kC;
constexpr long N_QKV   = (long)kB*kTA*3*kC;
constexpr long N_Y     = N_HLN;
constexpr long N_HFC   = (long)kB*kTA*4*kC;
constexpr long N_OUT   = N_X;
constexpr long N_KEYS  = N_X;
constexpr long N_HH    = N_H;
constexpr long N_DP    = N_X;
constexpr long N_DPT   = N_X;
constexpr long N_HHT   = N_H;
constexpr long N_DZT   = N_H;
constexpr long N_KEYST = N_X;
constexpr long N_W1T   = (long)kB*kHID*kC;
constexpr long N_SQW   = (long)kC*kC;
constexpr long N_ATTNW = (long)3*kC*kC;
constexpr long N_FCW   = (long)4*kC*kC;
constexpr long N_MLPW  = (long)4*kC*kC;
constexpr long N_W0    = (long)kB*kHID*kC;
constexpr long N_W1    = (long)kB*kC*kHID;

__device__ __nv_bfloat16 s_x    [2*N_X];
__device__ __nv_bfloat16 s_q    [2*N_Q];
__device__ __nv_bfloat16 s_h    [2*N_H];
__device__ __nv_bfloat16 s_pool [2*N_POOL];
__device__ __nv_bfloat16 s_hln  [2*N_HLN];
__device__ __nv_bfloat16 s_qkv  [2*N_QKV];
__device__ __nv_bfloat16 s_y    [2*N_Y];
__device__ __nv_bfloat16 s_hfc  [2*N_HFC];
__device__ __nv_bfloat16 s_out  [2*N_OUT];
__device__ __nv_bfloat16 s_keys [2*N_KEYS];
__device__ __nv_bfloat16 s_hh   [2*N_HH];
__device__ __nv_bfloat16 s_dp   [2*N_DP];
__device__ __nv_bfloat16 s_dpT  [2*N_DPT];
__device__ __nv_bfloat16 s_hhT  [2*N_HHT];
__device__ __nv_bfloat16 s_dzT  [2*N_DZT];
__device__ __nv_bfloat16 s_keysT[2*N_KEYST];
__device__ __nv_bfloat16 s_w1T  [2*N_W1T];
__device__ __nv_bfloat16 s_qw   [2*N_SQW];
__device__ __nv_bfloat16 s_kw   [2*N_SQW];
__device__ __nv_bfloat16 s_vw   [2*N_SQW];
__device__ __nv_bfloat16 s_ow   [2*N_SQW];
__device__ __nv_bfloat16 s_projw[2*N_SQW];
__device__ __nv_bfloat16 s_attnw[2*N_ATTNW];
__device__ __nv_bfloat16 s_fcw  [2*N_FCW];
__device__ __nv_bfloat16 s_mlpw [2*N_MLPW];
__device__ __nv_bfloat16 s_w0   [2*N_W0];
__device__ __nv_bfloat16 s_w1   [2*N_W1];

// ---------------- helpers ----------------
__device__ __forceinline__ uint32_t smem_u32(const void* p) {
    uint32_t a;
    asm("{ .reg .u64 t; cvta.to.shared.u64 t, %1; cvt.u32.u64 %0, t; }" : "=r"(a) : "l"(p));
    return a;
}

__device__ __forceinline__ void bsplit(float v, __nv_bfloat16& h, __nv_bfloat16& l) {
    h = __float2bfloat16(v);
    l = __float2bfloat16(v - __bfloat162float(h));
}

__device__ __forceinline__ uint32_t packb(__nv_bfloat16 a, __nv_bfloat16 b) {
    __nv_bfloat162 t; t.x = a; t.y = b;
    return *(uint32_t*)&t;
}

__device__ __forceinline__ void mma_bf16(float* d, const uint32_t* a, const uint32_t* b) {
    asm volatile(
        "mma.sync.aligned.m16n8k16.row.col.f32.bf16.bf16.f32 "
        "{%0,%1,%2,%3}, {%4,%5,%6,%7}, {%8,%9}, {%0,%1,%2,%3};"
        : "+f"(d[0]), "+f"(d[1]), "+f"(d[2]), "+f"(d[3])
        : "r"(a[0]), "r"(a[1]), "r"(a[2]), "r"(a[3]), "r"(b[0]), "r"(b[1]));
}

__device__ __forceinline__ void ldsm4(uint32_t* r, uint32_t addr) {
    asm volatile("ldmatrix.sync.aligned.m8n8.x4.shared.b16 {%0,%1,%2,%3}, [%4];"
        : "=r"(r[0]), "=r"(r[1]), "=r"(r[2]), "=r"(r[3]) : "r"(addr));
}

// ---------------- bf16-split GEMM (NT, MBK=16, 48KB smem, 4 CTAs/SM) ----------------
constexpr int MBM = 128, MBN = 128, MBK = 16, MSTG = 3;
constexpr int STG_WORDS = 4096;
constexpr unsigned MSMEM = MSTG * STG_WORDS * 4;   // 49152

enum { EP_NONE=0, EP_SILU=1, EP_GELU=2, EP_DSILU=3, EP_SILUZ=4, EP_DPRED=5 };

template<int EPI, bool WF32, bool WSPLIT>
__global__ __launch_bounds__(256)
void bgemm_k(const __nv_bfloat16* __restrict__ A, const __nv_bfloat16* __restrict__ B,
             const float* __restrict__ bias, const float* __restrict__ res,
             float* __restrict__ C, __nv_bfloat16* __restrict__ Cs,
             float* __restrict__ C2, float scaleP,
             int M, int N, int K,
             long aPlane, long bPlane, long cPlane,
             long sA, long sB, long sBias, long sRes, long sC)
{
    extern __shared__ float smf[];
    const uint32_t smb = smem_u32(smf);

    const int tid = threadIdx.x, lane = tid & 31, wid = tid >> 5;
    const int gid = lane >> 2, tg = lane & 3;
    const int wm = wid & 3, wn = wid >> 2;
    const int bz = blockIdx.z;
    const int m0 = blockIdx.y * MBM, n0 = blockIdx.x * MBN;
    const int nk = K / MBK;
    const int lq = lane >> 3, lsub = lane & 7;

    float acc[2][8][4];
#pragma unroll
    for (int i=0;i<2;i++)
#pragma unroll
        for (int j=0;j<8;j++)
#pragma unroll
            for (int r=0;r<4;r++) acc[i][j][r] = 0.f;

    auto load_stage = [&](int stage, int kt) {
        const int sw = stage * STG_WORDS;
#pragma unroll
        for (int it=0; it<4; it++) {
            int id = tid + it*256;
            int p = id >> 8;
            int c = id & 255;
            int row = c >> 1, half = c & 1;
            const __nv_bfloat16* src;
            int sz = 16;
            if (p < 2) {
                int gm = m0 + row;
                int ok = gm < M;
                sz = ok ? 16 : 0;
                src = A + (p==1 ? aPlane : 0) + (long)bz*sA
                        + (long)(ok ? gm : 0)*K + kt*MBK + half*8;
            } else {
                src = B + (p==3 ? bPlane : 0) + (long)bz*sB
                        + (long)(n0 + row)*K + kt*MBK + half*8;
            }
            uint32_t dst = smb + (uint32_t)(sw + p*1024 + row*8
                              + ((half*4) ^ (((row>>2)&1)<<2)))*4u;
            asm volatile("cp.async.cg.shared.global [%0], [%1], 16, %2;\n"
                         :: "r"(dst), "l"(src), "r"(sz));
        }
        asm volatile("cp.async.commit_group;\n");
    };

    auto compute = [&](int stage) {
        const uint32_t sbase = smb + (uint32_t)stage * STG_WORDS * 4u;
        uint32_t ahi[2][4], alo[2][4];
#pragma unroll
        for (int i=0;i<2;i++) {
            int row = wm*32 + i*16 + lsub + (lq & 1)*8;
            uint32_t off = (uint32_t)(row*32 + (((lq>>1)*16) ^ ((row & 4) << 2)));
            ldsm4(ahi[i], sbase + off);
            ldsm4(alo[i], sbase + 4096u + off);
        }
#pragma unroll
        for (int jp=0;jp<4;jp++) {
            int rowb = wn*64 + jp*16 + (lq>>1)*8 + lsub;
            uint32_t offb = (uint32_t)(rowb*32 + (((lq&1)*16) ^ ((rowb & 4) << 2)));
            uint32_t bh[4], bl[4];
            ldsm4(bh, sbase + 8192u  + offb);
            ldsm4(bl, sbase + 12288u + offb);
            mma_bf16(acc[0][2*jp],   alo[0], bh);
            mma_bf16(acc[0][2*jp+1], alo[0], bh+2);
            mma_bf16(acc[1][2*jp],   alo[1], bh);
            mma_bf16(acc[1][2*jp+1], alo[1], bh+2);
            mma_bf16(acc[0][2*jp],   ahi[0], bl);
            mma_bf16(acc[0][2*jp+1], ahi[0], bl+2);
            mma_bf16(acc[1][2*jp],   ahi[1], bl);
            mma_bf16(acc[1][2*jp+1], ahi[1], bl+2);
            mma_bf16(acc[0][2*jp],   ahi[0], bh);
            mma_bf16(acc[0][2*jp+1], ahi[0], bh+2);
            mma_bf16(acc[1][2*jp],   ahi[1], bh);
            mma_bf16(acc[1][2*jp+1], ahi[1], bh+2);
        }
    };

    load_stage(0, 0);
    if (nk > 1) load_stage(1, 1);
    for (int kt = 0; kt < nk; kt++) {
        if (kt + 1 < nk) asm volatile("cp.async.wait_group 1;\n");
        else             asm volatile("cp.async.wait_group 0;\n");
        __syncthreads();
        compute(kt % MSTG);
        if (kt + 2 < nk) load_stage((kt + 2) % MSTG, kt + 2);
        __syncthreads();
    }

    const float* bp = bias ? bias + (long)bz*sBias : nullptr;
#pragma unroll
    for (int i=0;i<2;i++) {
#pragma unroll
        for (int half=0; half<2; half++) {
            int row = m0 + wm*32 + i*16 + gid + half*8;
            if (row >= M) continue;
            long rbase = (long)bz*sC + (long)row*N;
#pragma unroll
            for (int j=0;j<8;j++) {
                int col = n0 + wn*64 + j*8 + tg*2;
                float v0 = acc[i][j][half*2+0];
                float v1 = acc[i][j][half*2+1];
                if (bp) { v0 += bp[col]; v1 += bp[col+1]; }
                float z0v = v0, z1v = v1;
                if (EPI == EP_SILU || EPI == EP_SILUZ) {
                    v0 = v0 / (1.f + __expf(-v0));
                    v1 = v1 / (1.f + __expf(-v1));
                }
                if (EPI == EP_GELU) {
                    v0 = 0.5f*v0*(1.f + erff(v0*0.70710678118654752f));
                    v1 = 0.5f*v1*(1.f + erff(v1*0.70710678118654752f));
                }
                if (EPI == EP_DSILU) {
                    const float* zr = res + (long)bz*sRes + (long)row*N;
                    float z0 = zr[col], z1 = zr[col+1];
                    float s0 = 1.f/(1.f + __expf(-z0));
                    float s1 = 1.f/(1.f + __expf(-z1));
                    v0 *= s0*(1.f + z0*(1.f - s0));
                    v1 *= s1*(1.f + z1*(1.f - s1));
                }
                if (EPI == EP_DPRED) {
                    const float* vr = res + (long)bz*sRes + (long)row*N;
                    v0 = (v0 - vr[col])   * scaleP;
                    v1 = (v1 - vr[col+1]) * scaleP;
                }
                if (EPI == EP_NONE && res) {
                    const float* rrow = res + (long)bz*sRes + (long)row*N;
                    v0 += rrow[col]; v1 += rrow[col+1];
                }
                if (WF32) {
                    float2 o;
                    if (EPI == EP_SILUZ) { o.x = z0v; o.y = z1v; }
                    else                 { o.x = v0;  o.y = v1;  }
                    *(float2*)(C + rbase + col) = o;
                }
                if (EPI == EP_SILUZ && C2) {
                    float2 o; o.x = v0; o.y = v1;
                    *(float2*)(C2 + rbase + col) = o;
                }
                if (WSPLIT) {
                    __nv_bfloat16 h0,l0,h1,l1;
                    bsplit(v0, h0, l0); bsplit(v1, h1, l1);
                    *(__nv_bfloat162*)(Cs + rbase + col) = __nv_bfloat162{h0,h1};
                    *(__nv_bfloat162*)(Cs + cPlane + rbase + col) = __nv_bfloat162{l0,l1};
                }
            }
        }
    }
}

// ---------------- mma flash attention (split-bf16 qkv input) ----------------
__global__ __launch_bounds__(128)
void attn_mma_k(const __nv_bfloat16* __restrict__ qkvs, long qkvPlane,
                __nv_bfloat16* __restrict__ ys, long planeN)
{
    __shared__ __nv_bfloat16 Qh[64*72], Ql[64*72];
    __shared__ __nv_bfloat16 Kh[32*72], Kl[32*72];
    __shared__ __nv_bfloat16 Vh[64*40], Vl[64*40];

    const int bh = blockIdx.y;
    const int bb = bh / kH, hh = bh % kH;
    const int q0 = blockIdx.x * 64;
    const int tid = threadIdx.x, lane = tid & 31, wq = tid >> 5;
    const int gid = lane >> 2, tg = lane & 3;

    const __nv_bfloat16* qhiP = qkvs;
    const __nv_bfloat16* qloP = qkvs + qkvPlane;

    uint32_t* QwhW = (uint32_t*)Qh;  uint32_t* QwlW = (uint32_t*)Ql;
    uint32_t* KwhW = (uint32_t*)Kh;  uint32_t* KwlW = (uint32_t*)Kl;
    const uint32_t* Qwh = (const uint32_t*)Qh;
    const uint32_t* Qwl = (const uint32_t*)Ql;
    const uint32_t* Kwh = (const uint32_t*)Kh;
    const uint32_t* Kwl = (const uint32_t*)Kl;
    const uint32_t* Vwh = (const uint32_t*)Vh;
    const uint32_t* Vwl = (const uint32_t*)Vl;

#pragma unroll
    for (int it = 0; it < 16; it++) {
        int idx = tid + it*128;
        int row = idx >> 5, w = idx & 31;
        int qg = q0 + row;
        uint32_t vh = 0, vl = 0;
        if (qg < kTA) {
            long base = ((long)(bb*kTA + qg))*3*kC + hh*kDH + 2*w;
            vh = *(const uint32_t*)&qhiP[base];
            vl = *(const uint32_t*)&qloP[base];
        }
        QwhW[row*36 + w] = vh;
        QwlW[row*36 + w] = vl;
    }
    __syncthreads();

    uint32_t qh[4][4], ql[4][4];
    {
        int r0 = wq*16 + gid;
#pragma unroll
        for (int c = 0; c < 4; c++) {
            qh[c][0] = Qwh[ r0    *36 + 8*c + tg];
            qh[c][1] = Qwh[(r0+8) *36 + 8*c + tg];
            qh[c][2] = Qwh[ r0    *36 + 8*c + tg + 4];
            qh[c][3] = Qwh[(r0+8) *36 + 8*c + tg + 4];
            ql[c][0] = Qwl[ r0    *36 + 8*c + tg];
            ql[c][1] = Qwl[(r0+8) *36 + 8*c + tg];
            ql[c][2] = Qwl[ r0    *36 + 8*c + tg + 4];
            ql[c][3] = Qwl[(r0+8) *36 + 8*c + tg + 4];
        }
    }

    float yacc[8][4];
#pragma unroll
    for (int f=0; f<8; f++)
#pragma unroll
        for (int e=0; e<4; e++) yacc[f][e] = 0.f;
    float mrow0 = -INFINITY, mrow1 = -INFINITY, lrow0 = 0.f, lrow1 = 0.f;

    const int qrow0 = q0 + wq*16 + gid;
    const int qrow1 = qrow0 + 8;

    int ntiles = (q0 == 0) ? (kTA + 31)/32 : (q0/32 + 2);
    if (ntiles > (kTA + 31)/32) ntiles = (kTA + 31)/32;

    for (int kt = 0; kt < ntiles; kt++) {
        __syncthreads();
#pragma unroll
        for (int it = 0; it < 8; it++) {
            int idx = tid + it*128;
            int row = idx >> 5, w = idx & 31;
            int kg = kt*32 + row;
            uint32_t vh = 0, vl = 0;
            if (kg < kTA) {
                long base = ((long)(bb*kTA + kg))*3*kC + kC + hh*kDH + 2*w;
                vh = *(const uint32_t*)&qhiP[base];
                vl = *(const uint32_t*)&qloP[base];
            }
            KwhW[row*36 + w] = vh;
            KwlW[row*36 + w] = vl;
        }
#pragma unroll
        for (int it = 0; it < 8; it++) {
            int idx = tid + it*128;
            int row = idx >> 5, w = idx & 31;
            int kg = kt*32 + row;
            uint32_t vh = 0, vl = 0;
            if (kg < kTA) {
                long base = ((long)(bb*kTA + kg))*3*kC + 2*kC + hh*kDH + 2*w;
                vh = *(const uint32_t*)&qhiP[base];
                vl = *(const uint32_t*)&qloP[base];
            }
            __nv_bfloat162 h2 = *(__nv_bfloat162*)&vh;
            __nv_bfloat162 l2 = *(__nv_bfloat162*)&vl;
            Vh[(2*w)*40 + row]   = h2.x;
            Vh[(2*w+1)*40 + row] = h2.y;
            Vl[(2*w)*40 + row]   = l2.x;
            Vl[(2*w+1)*40 + row] = l2.y;
        }
        __syncthreads();

        float sfr[4][4];
#pragma unroll
        for (int j=0;j<4;j++)
#pragma unroll
            for (int e=0;e<4;e++) sfr[j][e] = 0.f;
#pragma unroll
        for (int j = 0; j < 4; j++) {
            int kr = 8*j + gid;
#pragma unroll
            for (int c = 0; c < 4; c++) {
                uint32_t kbh[2], kbl[2];
                kbh[0] = Kwh[kr*36 + 8*c + tg];
                kbh[1] = Kwh[kr*36 + 8*c + tg + 4];
                kbl[0] = Kwl[kr*36 + 8*c + tg];
                kbl[1] = Kwl[kr*36 + 8*c + tg + 4];
                mma_bf16(sfr[j], ql[c], kbh);
                mma_bf16(sfr[j], qh[c], kbl);
                mma_bf16(sfr[j], qh[c], kbh);
            }
        }

#pragma unroll
        for (int j = 0; j < 4; j++) {
#pragma unroll
            for (int e = 0; e < 4; e++) {
                int qg = (e < 2) ? qrow0 : qrow1;
                int kg = kt*32 + 8*j + 2*tg + (e & 1);
                float s = sfr[j][e] * 0.125f;
                if (kg >= kTA || (qg >= kPRE && kg > qg)) s = -INFINITY;
                sfr[j][e] = s;
            }
        }

        float mx0 = -INFINITY, mx1 = -INFINITY;
#pragma unroll
        for (int j = 0; j < 4; j++) {
            mx0 = fmaxf(mx0, fmaxf(sfr[j][0], sfr[j][1]));
            mx1 = fmaxf(mx1, fmaxf(sfr[j][2], sfr[j][3]));
        }
        mx0 = fmaxf(mx0, __shfl_xor_sync(0xffffffffu, mx0, 1));
        mx0 = fmaxf(mx0, __shfl_xor_sync(0xffffffffu, mx0, 2));
        mx1 = fmaxf(mx1, __shfl_xor_sync(0xffffffffu, mx1, 1));
        mx1 = fmaxf(mx1, __shfl_xor_sync(0xffffffffu, mx1, 2));
        float mn0 = fmaxf(mrow0, mx0), mn1 = fmaxf(mrow1, mx1);
        float corr0 = __expf(mrow0 - mn0), corr1 = __expf(mrow1 - mn1);

        float sum0 = 0.f, sum1 = 0.f;
        uint32_t ph[2][4], pl[2][4];
#pragma unroll
        for (int kc = 0; kc < 2; kc++) {
            float p00,p01,p02,p03, p10,p11,p12,p13;
            {
                int j = 2*kc;
                p00 = __expf(sfr[j][0] - mn0); p01 = __expf(sfr[j][1] - mn0);
                p02 = __expf(sfr[j][2] - mn1); p03 = __expf(sfr[j][3] - mn1);
                j = 2*kc + 1;
                p10 = __expf(sfr[j][0] - mn0); p11 = __expf(sfr[j][1] - mn0);
                p12 = __expf(sfr[j][2] - mn1); p13 = __expf(sfr[j][3] - mn1);
            }
            sum0 += p00 + p01 + p10 + p11;
            sum1 += p02 + p03 + p12 + p13;
            __nv_bfloat16 h0,l0,h1,l1;
            bsplit(p00,h0,l0); bsplit(p01,h1,l1);
            ph[kc][0] = packb(h0,h1); pl[kc][0] = packb(l0,l1);
            bsplit(p02,h0,l0); bsplit(p03,h1,l1);
            ph[kc][1] = packb(h0,h1); pl[kc][1] = packb(l0,l1);
            bsplit(p10,h0,l0); bsplit(p11,h1,l1);
            ph[kc][2] = packb(h0,h1); pl[kc][2] = packb(l0,l1);
            bsplit(p12,h0,l0); bsplit(p13,h1,l1);
            ph[kc][3] = packb(h0,h1); pl[kc][3] = packb(l0,l1);
        }
        sum0 += __shfl_xor_sync(0xffffffffu, sum0, 1);
        sum0 += __shfl_xor_sync(0xffffffffu, sum0, 2);
        sum1 += __shfl_xor_sync(0xffffffffu, sum1, 1);
        sum1 += __shfl_xor_sync(0xffffffffu, sum1, 2);
        lrow0 = lrow0*corr0 + sum0;
        lrow1 = lrow1*corr1 + sum1;
#pragma unroll
        for (int f = 0; f < 8; f++) {
            yacc[f][0] *= corr0; yacc[f][1] *= corr0;
            yacc[f][2] *= corr1; yacc[f][3] *= corr1;
        }
        mrow0 = mn0; mrow1 = mn1;

#pragma unroll
        for (int f = 0; f < 8; f++) {
            int dr = 8*f + gid;
#pragma unroll
            for (int kc = 0; kc < 2; kc++) {
                uint32_t vbh[2], vbl[2];
                vbh[0] = Vwh[dr*20 + 8*kc + tg];
                vbh[1] = Vwh[dr*20 + 8*kc + tg + 4];
                vbl[0] = Vwl[dr*20 + 8*kc + tg];
                vbl[1] = Vwl[dr*20 + 8*kc + tg + 4];
                mma_bf16(yacc[f], pl[kc], vbh);
                mma_bf16(yacc[f], ph[kc], vbl);
                mma_bf16(yacc[f], ph[kc], vbh);
            }
        }
    }

    float inv0 = 1.f / lrow0, inv1 = 1.f / lrow1;
#pragma unroll
    for (int f = 0; f < 8; f++) {
        int d = hh*kDH + 8*f + 2*tg;
        if (qrow0 < kTA) {
            long a = ((long)(bb*kTA + qrow0))*kC + d;
            __nv_bfloat16 h0,l0,h1,l1;
            bsplit(yacc[f][0]*inv0, h0, l0); bsplit(yacc[f][1]*inv0, h1, l1);
            *(__nv_bfloat162*)&ys[a] = __nv_bfloat162{h0,h1};
            *(__nv_bfloat162*)&ys[planeN + a] = __nv_bfloat162{l0,l1};
        }
        if (qrow1 < kTA) {
            long a = ((long)(bb*kTA + qrow1))*kC + d;
            __nv_bfloat16 h0,l0,h1,l1;
            bsplit(yacc[f][2]*inv1, h0, l0); bsplit(yacc[f][3]*inv1, h1, l1);
            *(__nv_bfloat162*)&ys[a] = __nv_bfloat162{h0,h1};
            *(__nv_bfloat162*)&ys[planeN + a] = __nv_bfloat162{l0,l1};
        }
    }
}

// ---------------- layernorm ----------------
__global__ __launch_bounds__(256)
void ln_k(const float* __restrict__ x, const float* __restrict__ w,
          const float* __restrict__ b, __nv_bfloat16* __restrict__ o, long planeN)
{
    const long row = blockIdx.x;
    const float* xr = x + row*kC;
    float s = 0.f, s2 = 0.f;
    for (int c = threadIdx.x; c < kC; c += 256) { float v = xr[c]; s += v; s2 += v*v; }
    __shared__ float sh[64];
#pragma unroll
    for (int off=16;off;off>>=1){ s += __shfl_xor_sync(0xffffffffu,s,off); s2 += __shfl_xor_sync(0xffffffffu,s2,off); }
    int wid = threadIdx.x >> 5, lane = threadIdx.x & 31;
    if (lane == 0){ sh[wid] = s; sh[32+wid] = s2; }
    __syncthreads();
    if (threadIdx.x < 32) {
        s  = (lane < 8) ? sh[lane]    : 0.f;
        s2 = (lane < 8) ? sh[32+lane] : 0.f;
#pragma unroll
        for (int off=4;off;off>>=1){ s += __shfl_xor_sync(0xffffffffu,s,off); s2 += __shfl_xor_sync(0xffffffffu,s2,off); }
        if (lane == 0){ sh[0] = s; sh[1] = s2; }
    }
    __syncthreads();
    float mean = sh[0] * (1.f/kC);
    float var  = sh[1] * (1.f/kC) - mean*mean;
    float rstd = rsqrtf(var + 1e-5f);
    for (int c = threadIdx.x; c < kC; c += 256) {
        float v = (xr[c]-mean)*rstd*w[c] + b[c];
        __nv_bfloat16 h,lo2; bsplit(v,h,lo2);
        o[row*kC + c] = h;
        o[planeN + row*kC + c] = lo2;
    }
}

// ---------------- small kernels ----------------
__global__ void pool_k(const float* __restrict__ mem, __nv_bfloat16* __restrict__ pooled, long planeN)
{
    const int bm = blockIdx.x;
    const int bI = bm / kM, mI = bm % kM;
    const int seg = kT / kM;
    const float* src = mem + ((long)bI*kT + (long)mI*seg)*kC;
    for (int c = threadIdx.x; c < kC; c += blockDim.x) {
        float s = 0.f;
        for (int t = 0; t < seg; t++) s += src[(long)t*kC + c];
        float v = s * (1.f/seg);
        __nv_bfloat16 h,l; bsplit(v,h,l);
        pooled[(long)bm*kC + c] = h;
        pooled[planeN + (long)bm*kC + c] = l;
    }
}

// concat prefix (persist) + x part: rows t in [kM, kTA)
__global__ void concat_xp_k(const float* __restrict__ pm, const float* __restrict__ x,
                            float* __restrict__ xa)
{
    long i = (long)blockIdx.x*blockDim.x + threadIdx.x;
    constexpr long TOT = (long)kB*(kTA-kM)*kC;
    if (i >= TOT) return;
    int c = (int)(i % kC); long r = i / kC;
    int t = (int)(r % (kTA-kM)); int b = (int)(r / (kTA-kM));
    int ta = t + kM;
    float v = (ta < kPRE) ? pm[(long)(ta-kM)*kC + c]
                          : x[((long)b*kT + (ta-kPRE))*kC + c];
    xa[((long)b*kTA + ta)*kC + c] = v;
}

// concat retr part: rows t in [0, kM)
__global__ void concat_retr_k(const float* __restrict__ retr, float* __restrict__ xa)
{
    long i = (long)blockIdx.x*blockDim.x + threadIdx.x;
    constexpr long TOT = (long)kB*kM*kC;
    if (i >= TOT) return;
    int c = (int)(i % kC); long r = i / kC;
    int t = (int)(r % kM); int b = (int)(r / kM);
    xa[((long)b*kTA + t)*kC + c] = retr[((long)b*kM + t)*kC + c];
}

__global__ void copyout_k(const float* __restrict__ xa2, float* __restrict__ out,
                          __nv_bfloat16* __restrict__ outs, long planeN)
{
    long i = (long)blockIdx.x*blockDim.x + threadIdx.x;
    if (i >= OUT_N) return;
    int c = (int)(i % kC); long r = i / kC; int t = (int)(r % kT); int b = (int)(r / kT);
    float v = xa2[((long)b*kTA + kPRE + t)*kC + c];
    out[i] = v;
    __nv_bfloat16 h,l; bsplit(v,h,l);
    outs[i] = h; outs[planeN + i] = l;
}

__global__ void zero_k(float* __restrict__ a, long n)
{
    long i = (long)blockIdx.x*blockDim.x + threadIdx.x;
    if (i < n) a[i] = 0.f;
}

__global__ void colsum_k(const float* __restrict__ in, float* __restrict__ out,
                         int rows, int cols, int rowsPerSeg)
{
    int z = blockIdx.z;
    in  += (long)z*rows*cols;
    out += (long)z*cols;
    int j = blockIdx.x*blockDim.x + threadIdx.x;
    if (j >= cols) return;
    int t0 = blockIdx.y * rowsPerSeg;
    int t1 = t0 + rowsPerSeg; if (t1 > rows) t1 = rows;
    float s = 0.f;
    for (int t = t0; t < t1; t++) s += in[(long)t*cols + j];
    atomicAdd(out + j, s);
}

__global__ void update_k(const float* __restrict__ w, const float* __restrict__ mom,
                         const float* __restrict__ g, float* __restrict__ outW,
                         float* __restrict__ outM, long n)
{
    long i = (long)blockIdx.x*blockDim.x + threadIdx.x;
    if (i >= n) return;
    float nm = kMU*mom[i] + g[i];
    outM[i] = nm;
    outW[i] = (1.f - kDECAY)*w[i] - kLR*nm;
}

// batched split: up to 12 (src,dst,n) jobs in one kernel
struct SplitJobs {
    const float* src[12];
    __nv_bfloat16* dst[12];
    long off[13];
    int cnt;
};

__global__ void msplit_k(SplitJobs js)
{
    long i = (long)blockIdx.x*blockDim.x + threadIdx.x;
    if (i >= js.off[js.cnt]) return;
    int k = 0;
    while (i >= js.off[k+1]) k++;
    long li = i - js.off[k];
    long n = js.off[k+1] - js.off[k];
    __nv_bfloat16 h,l; bsplit(js.src[k][li], h, l);
    js.dst[k][li] = h;
    js.dst[k][n + li] = l;
}

__global__ void transpose_split_k(const float* __restrict__ in, __nv_bfloat16* __restrict__ out,
                                  long planeN, int rows, int cols)
{
    __shared__ float tile[32][33];
    long zoff = (long)blockIdx.z * rows * cols;
    int c0 = blockIdx.x*32, r0 = blockIdx.y*32;
    int tx = threadIdx.x, ty = threadIdx.y;
#pragma unroll
    for (int i = 0; i < 32; i += 8) {
        int r = r0 + ty + i, c = c0 + tx;
        if (r < rows && c < cols) tile[ty+i][tx] = in[zoff + (long)r*cols + c];
    }
    __syncthreads();
#pragma unroll
    for (int i = 0; i < 32; i += 8) {
        int r = c0 + ty + i, c = r0 + tx;
        if (r < cols && c < rows) {
            __nv_bfloat16 h,l; bsplit(tile[tx][ty+i],h,l);
            out[zoff + (long)r*rows + c] = h;
            out[planeN + zoff + (long)r*rows + c] = l;
        }
    }
}

// ---------------- host side ----------------
template<int EPI, bool WF32, bool WSPLIT>
static void bgemm(cudaStream_t st,
                  const __nv_bfloat16* A, long aPlane, long sA,
                  const __nv_bfloat16* B, long bPlane, long sB,
                  const float* bias, long sBias, const float* res, long sRes,
                  float* C, __nv_bfloat16* Cs, long cPlane, long sC,
                  int M, int N, int K, int batch,
                  float* C2 = nullptr, float scaleP = 0.f)
{
    cudaFuncSetAttribute(bgemm_k<EPI,WF32,WSPLIT>,
                         cudaFuncAttributeMaxDynamicSharedMemorySize, MSMEM);
    dim3 grid(N/MBN, (M + MBM - 1)/MBM, batch);
    bgemm_k<EPI,WF32,WSPLIT><<<grid, 256, MSMEM, st>>>(A, B, bias, res, C, Cs, C2, scaleP,
        M, N, K, aPlane, bPlane, cPlane, sA, sB, sBias, sRes, sC);
}

static inline long cdiv(long a, long b){ return (a + b - 1)/b; }

#define GETF(var, sym) float* var; { void* _p=nullptr; cudaGetSymbolAddress(&_p, sym); var=(float*)_p; }
#define GETB(var, sym) __nv_bfloat16* var; { void* _p=nullptr; cudaGetSymbolAddress(&_p, sym); var=(__nv_bfloat16*)_p; }

extern "C" void kernel_launch(void* const* d_in, const int* in_sizes, int n_in,
                              void* d_out, int out_size)
{
    const float* x       = (const float*)d_in[0];
    const float* persist = (const float*)d_in[1];
    const float* ln1w    = (const float*)d_in[2];
    const float* ln1b    = (const float*)d_in[3];
    const float* ln2w    = (const float*)d_in[4];
    const float* ln2b    = (const float*)d_in[5];
    const float* attnw   = (const float*)d_in[6];
    const float* attnb   = (const float*)d_in[7];
    const float* projw   = (const float*)d_in[8];
    const float* projb   = (const float*)d_in[9];
    const float* fcw     = (const float*)d_in[10];
    const float* fcb     = (const float*)d_in[11];
    const float* mlpw    = (const float*)d_in[12];
    const float* mlpb    = (const float*)d_in[13];
    const float* qw      = (const float*)d_in[14];
    const float* qb      = (const float*)d_in[15];
    const float* kw      = (const float*)d_in[16];
    const float* kb      = (const float*)d_in[17];
    const float* vw      = (const float*)d_in[18];
    const float* vb      = (const float*)d_in[19];
    const float* ow      = (const float*)d_in[20];
    const float* ob      = (const float*)d_in[21];
    const float* memw0   = (const float*)d_in[22];
    const float* memb0   = (const float*)d_in[23];
    const float* memw1   = (const float*)d_in[24];
    const float* memb1   = (const float*)d_in[25];
    const float* momw0   = (const float*)d_in[26];
    const float* momb0   = (const float*)d_in[27];
    const float* momw1   = (const float*)d_in[28];
    const float* momb1   = (const float*)d_in[29];
    float* out = (float*)d_out;

    GETF(zbuf, g_h);    GETF(hh, g_hh);    GETF(memb, g_mem);  GETF(retr, g_retr);
    GETF(xa, g_xa);     GETF(xa2, g_xa2);  GETF(keys, g_keys);
    GETF(vals, g_vals); GETF(dh, g_dh);    GETF(gw0, g_gw0);   GETF(gw1, g_gw1);
    GETF(gb0, g_gb0);   GETF(gb1, g_gb1);

    GETB(px,    s_x);     GETB(pq,    s_q);     GETB(ph,    s_h);     GETB(ppool, s_pool);
    GETB(phln,  s_hln);   GETB(pqkv,  s_qkv);   GETB(py,    s_y);     GETB(phfc,  s_hfc);
    GETB(pout,  s_out);   GETB(pkeys, s_keys);  GETB(phh,   s_hh);    GETB(pdp,   s_dp);
    GETB(pdpT,  s_dpT);   GETB(phhT,  s_hhT);   GETB(pdzT,  s_dzT);   GETB(pkeysT,s_keysT);
    GETB(pw1T,  s_w1T);
    GETB(pqw,   s_qw);    GETB(pkw,   s_kw);    GETB(pvw,   s_vw);    GETB(pow_,  s_ow);
    GETB(pprojw,s_projw); GETB(pattnw,s_attnw); GETB(pfcw,  s_fcw);   GETB(pmlpw, s_mlpw);
    GETB(pw0,   s_w0);    GETB(pw1,   s_w1);

    const long sTC = (long)kT*kC, sTH = (long)kT*kHID;
    const long sW0 = (long)kHID*kC, sW1 = (long)kC*kHID;

    // lazy stream/event init (host resources only; identical GPU work every call)
    static cudaStream_t s2 = nullptr;
    static cudaEvent_t ev0, ev1, ev2, ev3, ev4, ev5, ev6, ev7;
    if (!s2) {
        cudaStreamCreateWithFlags(&s2, cudaStreamNonBlocking);
        cudaEventCreateWithFlags(&ev0, cudaEventDisableTiming);
        cudaEventCreateWithFlags(&ev1, cudaEventDisableTiming);
        cudaEventCreateWithFlags(&ev2, cudaEventDisableTiming);
        cudaEventCreateWithFlags(&ev3, cudaEventDisableTiming);
        cudaEventCreateWithFlags(&ev4, cudaEventDisableTiming);
        cudaEventCreateWithFlags(&ev5, cudaEventDisableTiming);
        cudaEventCreateWithFlags(&ev6, cudaEventDisableTiming);
        cudaEventCreateWithFlags(&ev7, cudaEventDisableTiming);
    }
    cudaStream_t s0 = 0;

    // ---- batched input splits (x + all weights) on main ----
    {
        SplitJobs js;
        int k = 0; long off = 0;
        auto add = [&](const float* s, __nv_bfloat16* d, long n){
            js.src[k] = s; js.dst[k] = d; js.off[k] = off; off += n; k++;
        };
        add(x,     px,     N_X);
        add(qw,    pqw,    N_SQW);
        add(kw,    pkw,    N_SQW);
        add(vw,    pvw,    N_SQW);
        add(ow,    pow_,   N_SQW);
        add(projw, pprojw, N_SQW);
        add(attnw, pattnw, N_ATTNW);
        add(fcw,   pfcw,   N_FCW);
        add(mlpw,  pmlpw,  N_MLPW);
        add(memw0, pw0,    N_W0);
        add(memw1, pw1,    N_W1);
        js.off[k] = off; js.cnt = k;
        msplit_k<<<(unsigned)cdiv(off,256),256,0,s0>>>(js);
    }
    // zero gb0 early on main (consumed much later)
    zero_k<<<(unsigned)cdiv(B0_N,256),256,0,s0>>>(gb0, B0_N);

    // fork: s2 does w1T transpose + prefix concat while main runs forward
    cudaEventRecord(ev0, s0);
    cudaStreamWaitEvent(s2, ev0, 0);
    transpose_split_k<<<dim3(kHID/32, kC/32, kB), dim3(32,8), 0, s2>>>(memw1, pw1T, N_W1T, kC, kHID);
    {
        long n = (long)kB*(kTA-kM)*kC;
        concat_xp_k<<<(unsigned)cdiv(n,256),256,0,s2>>>(persist, x, xa);
    }
    cudaEventRecord(ev1, s2);

    // ---- forward memory read path (main) ----
    bgemm<EP_NONE,false,true>(s0, px,N_X,0, pqw,N_SQW,0, qb,0, nullptr,0,
                              nullptr, pq,N_Q, 0, kB*kT, kC, kC, 1);
    bgemm<EP_SILU,false,true>(s0, pq,N_Q,sTC, pw0,N_W0,sW0, memb0,kHID, nullptr,0,
                              nullptr, ph,N_H, sTH, kT, kHID, kC, kB);
    bgemm<EP_NONE,true,false>(s0, ph,N_H,sTH, pw1,N_W1,sW1, memb1,kC, nullptr,0,
                              memb, nullptr,0, sTC, kT, kC, kHID, kB);
    pool_k<<<kB*kM, 256, 0, s0>>>(memb, ppool, N_POOL);
    bgemm<EP_NONE,true,false>(s0, ppool,N_POOL,0, pow_,N_SQW,0, ob,0, nullptr,0,
                              retr, nullptr,0, 0, kB*kM, kC, kC, 1);
    {
        long n = (long)kB*kM*kC;
        concat_retr_k<<<(unsigned)cdiv(n,256),256,0,s0>>>(retr, xa);
    }
    cudaStreamWaitEvent(s0, ev1, 0);   // prefix concat must be done before ln1

    // ---- transformer block (main) ----
    ln_k<<<kB*kTA,256,0,s0>>>(xa, ln1w, ln1b, phln, N_HLN);
    bgemm<EP_NONE,false,true>(s0, phln,N_HLN,0, pattnw,N_ATTNW,0, attnb,0, nullptr,0,
                              nullptr, pqkv,N_QKV, 0, kB*kTA, 3*kC, kC, 1);
    attn_mma_k<<<dim3((kTA+63)/64, kB*kH), 128, 0, s0>>>(pqkv, N_QKV, py, N_Y);
    bgemm<EP_NONE,true,false>(s0, py,N_Y,0, pprojw,N_SQW,0, projb,0, xa,0,
                              xa2, nullptr,0, 0, kB*kTA, kC, kC, 1);
    ln_k<<<kB*kTA,256,0,s0>>>(xa2, ln2w, ln2b, phln, N_HLN);
    bgemm<EP_GELU,false,true>(s0, phln,N_HLN,0, pfcw,N_FCW,0, fcb,0, nullptr,0,
                              nullptr, phfc,N_HFC, 0, kB*kTA, 4*kC, kC, 1);
    bgemm<EP_NONE,true,false>(s0, phfc,N_HFC,0, pmlpw,N_MLPW,0, mlpb,0, xa2,0,
                              xa2, nullptr,0, 0, kB*kTA, kC, 4*kC, 1);
    copyout_k<<<(unsigned)cdiv(OUT_N,256),256,0,s0>>>(xa2, out, pout, N_OUT);

    // ---- memory write path ----
    // fork: vals GEMM on s2 while keys+z run on main
    cudaEventRecord(ev2, s0);
    cudaStreamWaitEvent(s2, ev2, 0);
    bgemm<EP_NONE,true,false>(s2, pout,N_OUT,0, pvw,N_SQW,0, vb,0, nullptr,0,
                              vals, nullptr,0, 0, kB*kT, kC, kC, 1);
    cudaEventRecord(ev3, s2);

    bgemm<EP_NONE,true,true>(s0, pout,N_OUT,0, pkw,N_SQW,0, kb,0, nullptr,0,
                             keys, pkeys,N_KEYS, 0, kB*kT, kC, kC, 1);
    cudaEventRecord(ev4, s0);
    // keysT transpose on s2 after keys done (runs alongside z GEMM on main)
    cudaStreamWaitEvent(s2, ev4, 0);
    transpose_split_k<<<dim3(kC/32, kT/32, kB), dim3(32,8), 0, s2>>>(keys, pkeysT, N_KEYST, kT, kC);
    cudaEventRecord(ev5, s2);

    // z = keys@w0^T + b0 ; fused silu
    bgemm<EP_SILUZ,true,true>(s0, pkeys,N_KEYS,sTC, pw0,N_W0,sW0, memb0,kHID, nullptr,0,
                              zbuf, phh,N_HH, sTH, kT, kHID, kC, kB, hh);
    cudaStreamWaitEvent(s0, ev3, 0);   // vals needed by dpred
    // dpred = (hh@w1^T + b1 - vals) * scale
    bgemm<EP_DPRED,true,true>(s0, phh,N_HH,sTH, pw1,N_W1,sW1, memb1,kC, vals,sTC,
                              memb, pdp,N_DP, sTC, kT, kC, kHID, kB,
                              nullptr, 2.f/((float)kT*(float)kC));
    cudaEventRecord(ev6, s0);

    // s2 branch: gb1 + dpT/hhT transposes + gw1 + w1/b1 updates
    cudaStreamWaitEvent(s2, ev6, 0);
    zero_k<<<(unsigned)cdiv(B1_N,256),256,0,s2>>>(gb1, B1_N);
    colsum_k<<<dim3((kC+255)/256, 8, kB),256,0,s2>>>(memb, gb1, kT, kC, kT/8);
    transpose_split_k<<<dim3(kC/32,  kT/32, kB), dim3(32,8), 0, s2>>>(memb, pdpT, N_DPT, kT, kC);
    transpose_split_k<<<dim3(kHID/32,kT/32, kB), dim3(32,8), 0, s2>>>(hh,   phhT, N_HHT, kT, kHID);
    bgemm<EP_NONE,true,false>(s2, pdpT,N_DPT,sTC, phhT,N_HHT,sTH, nullptr,0, nullptr,0,
                              gw1, nullptr,0, sW1, kC, kHID, kT, kB);
    update_k<<<(unsigned)cdiv(W1_N,256),256,0,s2>>>(memw1, momw1, gw1, out+OFF_NW1, out+OFF_NMW1, W1_N);
    update_k<<<(unsigned)cdiv(B1_N,256),256,0,s2>>>(memb1, momb1, gb1, out+OFF_NB1, out+OFF_NMB1, B1_N);
    cudaEventRecord(ev7, s2);

    // main branch: dh + gb0 + dzT + gw0 + w0/b0 updates
    bgemm<EP_DSILU,true,false>(s0, pdp,N_DP,sTC, pw1T,N_W1T,sW0, nullptr,0, zbuf,sTH,
                               dh, nullptr,0, sTH, kT, kHID, kC, kB);
    colsum_k<<<dim3((kHID+255)/256, 8, kB),256,0,s0>>>(dh, gb0, kT, kHID, kT/8);
    update_k<<<(unsigned)cdiv(B0_N,256),256,0,s0>>>(memb0, momb0, gb0, out+OFF_NB0, out+OFF_NMB0, B0_N);
    transpose_split_k<<<dim3(kHID/32,kT/32, kB), dim3(32,8), 0, s0>>>(dh, pdzT, N_DZT, kT, kHID);
    cudaStreamWaitEvent(s0, ev5, 0);   // keysT needed by gw0
    bgemm<EP_NONE,true,false>(s0, pdzT,N_DZT,sTH, pkeysT,N_KEYST,sTC, nullptr,0, nullptr,0,
                              gw0, nullptr,0, sW0, kHID, kC, kT, kB);
    update_k<<<(unsigned)cdiv(W0_N,256),256,0,s0>>>(memw0, momw0, gw0, out+OFF_NW0, out+OFF_NMW0, W0_N);

    // join s2 into main before graph end
    cudaStreamWaitEvent(s0, ev7, 0);

    (void)in_sizes; (void)n_in; (void)out_size;
}

// round 13
// speedup vs baseline: 1.0688x; 1.0008x over previous
#include <cuda_runtime.h>
#include <cuda_bf16.h>
#include <math.h>
#include <stdint.h>

// ---------------- problem constants ----------------
constexpr int kB   = 8;
constexpr int kT   = 1024;
constexpr int kC   = 768;
constexpr int kH   = 12;
constexpr int kDH  = 64;
constexpr int kHID = 1536;   // 2*C
constexpr int kM   = 16;
constexpr int kP   = 4;
constexpr int kPRE = kM + kP;      // 20
constexpr int kTA  = kT + kPRE;    // 1044
constexpr float kLR = 0.01f, kMU = 0.9f, kDECAY = 0.001f;

constexpr long OUT_N = (long)kB*kT*kC;
constexpr long W0_N  = (long)kB*kHID*kC;
constexpr long B0_N  = (long)kB*kHID;
constexpr long W1_N  = (long)kB*kC*kHID;
constexpr long B1_N  = (long)kB*kC;
constexpr long OFF_NW0  = OUT_N;
constexpr long OFF_NB0  = OFF_NW0  + W0_N;
constexpr long OFF_NW1  = OFF_NB0  + B0_N;
constexpr long OFF_NB1  = OFF_NW1  + W1_N;
constexpr long OFF_NMW0 = OFF_NB1  + B1_N;
constexpr long OFF_NMB0 = OFF_NMW0 + W0_N;
constexpr long OFF_NMW1 = OFF_NMB0 + B0_N;
constexpr long OFF_NMB1 = OFF_NMW1 + W1_N;

// ---------------- f32 scratch ----------------
__device__ float g_h    [(long)kB*kT*kHID];
__device__ float g_hh   [(long)kB*kT*kHID];
__device__ float g_mem  [(long)kB*kT*kC];
__device__ float g_retr [(long)kB*kM*kC];
__device__ float g_xa   [(long)kB*kTA*kC];
__device__ float g_xa2  [(long)kB*kTA*kC];
__device__ float g_keys [(long)kB*kT*kC];
__device__ float g_vals [(long)kB*kT*kC];
__device__ float g_dh   [(long)kB*kT*kHID];
__device__ float g_gw0  [(long)kB*kHID*kC];
__device__ float g_gw1  [(long)kB*kC*kHID];
__device__ float g_gb0  [(long)kB*kHID];
__device__ float g_gb1  [(long)kB*kC];

// ---------------- bf16 split planes ----------------
constexpr long N_X     = (long)kB*kT*kC;
constexpr long N_Q     = N_X;
constexpr long N_H     = (long)kB*kT*kHID;
constexpr long N_POOL  = (long)kB*kM*kC;
constexpr long N_HLN   = (long)kB*kTA*kC;
constexpr long N_QKV   = (long)kB*kTA*3*kC;
constexpr long N_Y     = N_HLN;
constexpr long N_HFC   = (long)kB*kTA*4*kC;
constexpr long N_OUT   = N_X;
constexpr long N_KEYS  = N_X;
constexpr long N_HH    = N_H;
constexpr long N_DP    = N_X;
constexpr long N_DPT   = N_X;
constexpr long N_HHT   = N_H;
constexpr long N_DZT   = N_H;
constexpr long N_KEYST = N_X;
constexpr long N_W1T   = (long)kB*kHID*kC;
constexpr long N_SQW   = (long)kC*kC;
constexpr long N_ATTNW = (long)3*kC*kC;
constexpr long N_FCW   = (long)4*kC*kC;
constexpr long N_MLPW  = (long)4*kC*kC;
constexpr long N_W0    = (long)kB*kHID*kC;
constexpr long N_W1    = (long)kB*kC*kHID;

__device__ __nv_bfloat16 s_x    [2*N_X];
__device__ __nv_bfloat16 s_q    [2*N_Q];
__device__ __nv_bfloat16 s_h    [2*N_H];
__device__ __nv_bfloat16 s_pool [2*N_POOL];
__device__ __nv_bfloat16 s_hln  [2*N_HLN];
__device__ __nv_bfloat16 s_qkv  [2*N_QKV];
__device__ __nv_bfloat16 s_y    [2*N_Y];
__device__ __nv_bfloat16 s_hfc  [2*N_HFC];
__device__ __nv_bfloat16 s_out  [2*N_OUT];
__device__ __nv_bfloat16 s_keys [2*N_KEYS];
__device__ __nv_bfloat16 s_hh   [2*N_HH];
__device__ __nv_bfloat16 s_dp   [2*N_DP];
__device__ __nv_bfloat16 s_dpT  [2*N_DPT];
__device__ __nv_bfloat16 s_hhT  [2*N_HHT];
__device__ __nv_bfloat16 s_dzT  [2*N_DZT];
__device__ __nv_bfloat16 s_keysT[2*N_KEYST];
__device__ __nv_bfloat16 s_w1T  [2*N_W1T];
__device__ __nv_bfloat16 s_qw   [2*N_SQW];
__device__ __nv_bfloat16 s_kw   [2*N_SQW];
__device__ __nv_bfloat16 s_vw   [2*N_SQW];
__device__ __nv_bfloat16 s_ow   [2*N_SQW];
__device__ __nv_bfloat16 s_projw[2*N_SQW];
__device__ __nv_bfloat16 s_attnw[2*N_ATTNW];
__device__ __nv_bfloat16 s_fcw  [2*N_FCW];
__device__ __nv_bfloat16 s_mlpw [2*N_MLPW];
__device__ __nv_bfloat16 s_w0   [2*N_W0];
__device__ __nv_bfloat16 s_w1   [2*N_W1];

// ---------------- helpers ----------------
__device__ __forceinline__ uint32_t smem_u32(const void* p) {
    uint32_t a;
    asm("{ .reg .u64 t; cvta.to.shared.u64 t, %1; cvt.u32.u64 %0, t; }" : "=r"(a) : "l"(p));
    return a;
}

__device__ __forceinline__ void bsplit(float v, __nv_bfloat16& h, __nv_bfloat16& l) {
    h = __float2bfloat16(v);
    l = __float2bfloat16(v - __bfloat162float(h));
}

__device__ __forceinline__ uint32_t packb(__nv_bfloat16 a, __nv_bfloat16 b) {
    __nv_bfloat162 t; t.x = a; t.y = b;
    return *(uint32_t*)&t;
}

__device__ __forceinline__ void mma_bf16(float* d, const uint32_t* a, const uint32_t* b) {
    asm volatile(
        "mma.sync.aligned.m16n8k16.row.col.f32.bf16.bf16.f32 "
        "{%0,%1,%2,%3}, {%4,%5,%6,%7}, {%8,%9}, {%0,%1,%2,%3};"
        : "+f"(d[0]), "+f"(d[1]), "+f"(d[2]), "+f"(d[3])
        : "r"(a[0]), "r"(a[1]), "r"(a[2]), "r"(a[3]), "r"(b[0]), "r"(b[1]));
}

__device__ __forceinline__ void ldsm4(uint32_t* r, uint32_t addr) {
    asm volatile("ldmatrix.sync.aligned.m8n8.x4.shared.b16 {%0,%1,%2,%3}, [%4];"
        : "=r"(r[0]), "=r"(r[1]), "=r"(r[2]), "=r"(r[3]) : "r"(addr));
}

// ---------------- bf16-split GEMM (NT, MBK=16, 48KB smem) ----------------
constexpr int MBM = 128, MBN = 128, MBK = 16, MSTG = 3;
constexpr int STG_WORDS = 4096;
constexpr unsigned MSMEM = MSTG * STG_WORDS * 4;

enum { EP_NONE=0, EP_SILU=1, EP_GELU=2, EP_DSILU=3, EP_SILUZ=4, EP_DPRED=5 };

template<int EPI, bool WF32, bool WSPLIT>
__global__ __launch_bounds__(256)
void bgemm_k(const __nv_bfloat16* __restrict__ A, const __nv_bfloat16* __restrict__ B,
             const float* __restrict__ bias, const float* __restrict__ res,
             float* __restrict__ C, __nv_bfloat16* __restrict__ Cs,
             float* __restrict__ C2, float scaleP,
             int M, int N, int K,
             long aPlane, long bPlane, long cPlane,
             long sA, long sB, long sBias, long sRes, long sC)
{
    extern __shared__ float smf[];
    const uint32_t smb = smem_u32(smf);

    const int tid = threadIdx.x, lane = tid & 31, wid = tid >> 5;
    const int gid = lane >> 2, tg = lane & 3;
    const int wm = wid & 3, wn = wid >> 2;
    const int bz = blockIdx.z;
    const int m0 = blockIdx.y * MBM, n0 = blockIdx.x * MBN;
    const int nk = K / MBK;
    const int lq = lane >> 3, lsub = lane & 7;

    float acc[2][8][4];
#pragma unroll
    for (int i=0;i<2;i++)
#pragma unroll
        for (int j=0;j<8;j++)
#pragma unroll
            for (int r=0;r<4;r++) acc[i][j][r] = 0.f;

    auto load_stage = [&](int stage, int kt) {
        const int sw = stage * STG_WORDS;
#pragma unroll
        for (int it=0; it<4; it++) {
            int id = tid + it*256;
            int p = id >> 8;
            int c = id & 255;
            int row = c >> 1, half = c & 1;
            const __nv_bfloat16* src;
            int sz = 16;
            if (p < 2) {
                int gm = m0 + row;
                int ok = gm < M;
                sz = ok ? 16 : 0;
                src = A + (p==1 ? aPlane : 0) + (long)bz*sA
                        + (long)(ok ? gm : 0)*K + kt*MBK + half*8;
            } else {
                src = B + (p==3 ? bPlane : 0) + (long)bz*sB
                        + (long)(n0 + row)*K + kt*MBK + half*8;
            }
            uint32_t dst = smb + (uint32_t)(sw + p*1024 + row*8
                              + ((half*4) ^ (((row>>2)&1)<<2)))*4u;
            asm volatile("cp.async.cg.shared.global [%0], [%1], 16, %2;\n"
                         :: "r"(dst), "l"(src), "r"(sz));
        }
        asm volatile("cp.async.commit_group;\n");
    };

    auto compute = [&](int stage) {
        const uint32_t sbase = smb + (uint32_t)stage * STG_WORDS * 4u;
        uint32_t ahi[2][4], alo[2][4];
#pragma unroll
        for (int i=0;i<2;i++) {
            int row = wm*32 + i*16 + lsub + (lq & 1)*8;
            uint32_t off = (uint32_t)(row*32 + (((lq>>1)*16) ^ ((row & 4) << 2)));
            ldsm4(ahi[i], sbase + off);
            ldsm4(alo[i], sbase + 4096u + off);
        }
#pragma unroll
        for (int jp=0;jp<4;jp++) {
            int rowb = wn*64 + jp*16 + (lq>>1)*8 + lsub;
            uint32_t offb = (uint32_t)(rowb*32 + (((lq&1)*16) ^ ((rowb & 4) << 2)));
            uint32_t bh[4], bl[4];
            ldsm4(bh, sbase + 8192u  + offb);
            ldsm4(bl, sbase + 12288u + offb);
            mma_bf16(acc[0][2*jp],   alo[0], bh);
            mma_bf16(acc[0][2*jp+1], alo[0], bh+2);
            mma_bf16(acc[1][2*jp],   alo[1], bh);
            mma_bf16(acc[1][2*jp+1], alo[1], bh+2);
            mma_bf16(acc[0][2*jp],   ahi[0], bl);
            mma_bf16(acc[0][2*jp+1], ahi[0], bl+2);
            mma_bf16(acc[1][2*jp],   ahi[1], bl);
            mma_bf16(acc[1][2*jp+1], ahi[1], bl+2);
            mma_bf16(acc[0][2*jp],   ahi[0], bh);
            mma_bf16(acc[0][2*jp+1], ahi[0], bh+2);
            mma_bf16(acc[1][2*jp],   ahi[1], bh);
            mma_bf16(acc[1][2*jp+1], ahi[1], bh+2);
        }
    };

    load_stage(0, 0);
    if (nk > 1) load_stage(1, 1);
    for (int kt = 0; kt < nk; kt++) {
        if (kt + 1 < nk) asm volatile("cp.async.wait_group 1;\n");
        else             asm volatile("cp.async.wait_group 0;\n");
        __syncthreads();
        compute(kt % MSTG);
        if (kt + 2 < nk) load_stage((kt + 2) % MSTG, kt + 2);
        __syncthreads();
    }

    const float* bp = bias ? bias + (long)bz*sBias : nullptr;
#pragma unroll
    for (int i=0;i<2;i++) {
#pragma unroll
        for (int half=0; half<2; half++) {
            int row = m0 + wm*32 + i*16 + gid + half*8;
            if (row >= M) continue;
            long rbase = (long)bz*sC + (long)row*N;
#pragma unroll
            for (int j=0;j<8;j++) {
                int col = n0 + wn*64 + j*8 + tg*2;
                float v0 = acc[i][j][half*2+0];
                float v1 = acc[i][j][half*2+1];
                if (bp) { v0 += bp[col]; v1 += bp[col+1]; }
                float z0v = v0, z1v = v1;
                if (EPI == EP_SILU || EPI == EP_SILUZ) {
                    v0 = v0 / (1.f + __expf(-v0));
                    v1 = v1 / (1.f + __expf(-v1));
                }
                if (EPI == EP_GELU) {
                    v0 = 0.5f*v0*(1.f + erff(v0*0.70710678118654752f));
                    v1 = 0.5f*v1*(1.f + erff(v1*0.70710678118654752f));
                }
                if (EPI == EP_DSILU) {
                    const float* zr = res + (long)bz*sRes + (long)row*N;
                    float z0 = zr[col], z1 = zr[col+1];
                    float s0 = 1.f/(1.f + __expf(-z0));
                    float s1 = 1.f/(1.f + __expf(-z1));
                    v0 *= s0*(1.f + z0*(1.f - s0));
                    v1 *= s1*(1.f + z1*(1.f - s1));
                }
                if (EPI == EP_DPRED) {
                    const float* vr = res + (long)bz*sRes + (long)row*N;
                    v0 = (v0 - vr[col])   * scaleP;
                    v1 = (v1 - vr[col+1]) * scaleP;
                }
                if (EPI == EP_NONE && res) {
                    const float* rrow = res + (long)bz*sRes + (long)row*N;
                    v0 += rrow[col]; v1 += rrow[col+1];
                }
                if (WF32) {
                    float2 o;
                    if (EPI == EP_SILUZ) { o.x = z0v; o.y = z1v; }
                    else                 { o.x = v0;  o.y = v1;  }
                    *(float2*)(C + rbase + col) = o;
                }
                if (EPI == EP_SILUZ && C2) {
                    float2 o; o.x = v0; o.y = v1;
                    *(float2*)(C2 + rbase + col) = o;
                }
                if (WSPLIT) {
                    __nv_bfloat16 h0,l0,h1,l1;
                    bsplit(v0, h0, l0); bsplit(v1, h1, l1);
                    *(__nv_bfloat162*)(Cs + rbase + col) = __nv_bfloat162{h0,h1};
                    *(__nv_bfloat162*)(Cs + cPlane + rbase + col) = __nv_bfloat162{l0,l1};
                }
            }
        }
    }
}

// ---------------- mma flash attention ----------------
__global__ __launch_bounds__(128)
void attn_mma_k(const __nv_bfloat16* __restrict__ qkvs, long qkvPlane,
                __nv_bfloat16* __restrict__ ys, long planeN)
{
    __shared__ __nv_bfloat16 Qh[64*72], Ql[64*72];
    __shared__ __nv_bfloat16 Kh[32*72], Kl[32*72];
    __shared__ __nv_bfloat16 Vh[64*40], Vl[64*40];

    const int bh = blockIdx.y;
    const int bb = bh / kH, hh = bh % kH;
    const int q0 = blockIdx.x * 64;
    const int tid = threadIdx.x, lane = tid & 31, wq = tid >> 5;
    const int gid = lane >> 2, tg = lane & 3;

    const __nv_bfloat16* qhiP = qkvs;
    const __nv_bfloat16* qloP = qkvs + qkvPlane;

    uint32_t* QwhW = (uint32_t*)Qh;  uint32_t* QwlW = (uint32_t*)Ql;
    uint32_t* KwhW = (uint32_t*)Kh;  uint32_t* KwlW = (uint32_t*)Kl;
    const uint32_t* Qwh = (const uint32_t*)Qh;
    const uint32_t* Qwl = (const uint32_t*)Ql;
    const uint32_t* Kwh = (const uint32_t*)Kh;
    const uint32_t* Kwl = (const uint32_t*)Kl;
    const uint32_t* Vwh = (const uint32_t*)Vh;
    const uint32_t* Vwl = (const uint32_t*)Vl;

#pragma unroll
    for (int it = 0; it < 16; it++) {
        int idx = tid + it*128;
        int row = idx >> 5, w = idx & 31;
        int qg = q0 + row;
        uint32_t vh = 0, vl = 0;
        if (qg < kTA) {
            long base = ((long)(bb*kTA + qg))*3*kC + hh*kDH + 2*w;
            vh = *(const uint32_t*)&qhiP[base];
            vl = *(const uint32_t*)&qloP[base];
        }
        QwhW[row*36 + w] = vh;
        QwlW[row*36 + w] = vl;
    }
    __syncthreads();

    uint32_t qh[4][4], ql[4][4];
    {
        int r0 = wq*16 + gid;
#pragma unroll
        for (int c = 0; c < 4; c++) {
            qh[c][0] = Qwh[ r0    *36 + 8*c + tg];
            qh[c][1] = Qwh[(r0+8) *36 + 8*c + tg];
            qh[c][2] = Qwh[ r0    *36 + 8*c + tg + 4];
            qh[c][3] = Qwh[(r0+8) *36 + 8*c + tg + 4];
            ql[c][0] = Qwl[ r0    *36 + 8*c + tg];
            ql[c][1] = Qwl[(r0+8) *36 + 8*c + tg];
            ql[c][2] = Qwl[ r0    *36 + 8*c + tg + 4];
            ql[c][3] = Qwl[(r0+8) *36 + 8*c + tg + 4];
        }
    }

    float yacc[8][4];
#pragma unroll
    for (int f=0; f<8; f++)
#pragma unroll
        for (int e=0; e<4; e++) yacc[f][e] = 0.f;
    float mrow0 = -INFINITY, mrow1 = -INFINITY, lrow0 = 0.f, lrow1 = 0.f;

    const int qrow0 = q0 + wq*16 + gid;
    const int qrow1 = qrow0 + 8;

    int ntiles = (q0 == 0) ? (kTA + 31)/32 : (q0/32 + 2);
    if (ntiles > (kTA + 31)/32) ntiles = (kTA + 31)/32;

    for (int kt = 0; kt < ntiles; kt++) {
        __syncthreads();
#pragma unroll
        for (int it = 0; it < 8; it++) {
            int idx = tid + it*128;
            int row = idx >> 5, w = idx & 31;
            int kg = kt*32 + row;
            uint32_t vh = 0, vl = 0;
            if (kg < kTA) {
                long base = ((long)(bb*kTA + kg))*3*kC + kC + hh*kDH + 2*w;
                vh = *(const uint32_t*)&qhiP[base];
                vl = *(const uint32_t*)&qloP[base];
            }
            KwhW[row*36 + w] = vh;
            KwlW[row*36 + w] = vl;
        }
#pragma unroll
        for (int it = 0; it < 8; it++) {
            int idx = tid + it*128;
            int row = idx >> 5, w = idx & 31;
            int kg = kt*32 + row;
            uint32_t vh = 0, vl = 0;
            if (kg < kTA) {
                long base = ((long)(bb*kTA + kg))*3*kC + 2*kC + hh*kDH + 2*w;
                vh = *(const uint32_t*)&qhiP[base];
                vl = *(const uint32_t*)&qloP[base];
            }
            __nv_bfloat162 h2 = *(__nv_bfloat162*)&vh;
            __nv_bfloat162 l2 = *(__nv_bfloat162*)&vl;
            Vh[(2*w)*40 + row]   = h2.x;
            Vh[(2*w+1)*40 + row] = h2.y;
            Vl[(2*w)*40 + row]   = l2.x;
            Vl[(2*w+1)*40 + row] = l2.y;
        }
        __syncthreads();

        float sfr[4][4];
#pragma unroll
        for (int j=0;j<4;j++)
#pragma unroll
            for (int e=0;e<4;e++) sfr[j][e] = 0.f;
#pragma unroll
        for (int j = 0; j < 4; j++) {
            int kr = 8*j + gid;
#pragma unroll
            for (int c = 0; c < 4; c++) {
                uint32_t kbh[2], kbl[2];
                kbh[0] = Kwh[kr*36 + 8*c + tg];
                kbh[1] = Kwh[kr*36 + 8*c + tg + 4];
                kbl[0] = Kwl[kr*36 + 8*c + tg];
                kbl[1] = Kwl[kr*36 + 8*c + tg + 4];
                mma_bf16(sfr[j], ql[c], kbh);
                mma_bf16(sfr[j], qh[c], kbl);
                mma_bf16(sfr[j], qh[c], kbh);
            }
        }

#pragma unroll
        for (int j = 0; j < 4; j++) {
#pragma unroll
            for (int e = 0; e < 4; e++) {
                int qg = (e < 2) ? qrow0 : qrow1;
                int kg = kt*32 + 8*j + 2*tg + (e & 1);
                float s = sfr[j][e] * 0.125f;
                if (kg >= kTA || (qg >= kPRE && kg > qg)) s = -INFINITY;
                sfr[j][e] = s;
            }
        }

        float mx0 = -INFINITY, mx1 = -INFINITY;
#pragma unroll
        for (int j = 0; j < 4; j++) {
            mx0 = fmaxf(mx0, fmaxf(sfr[j][0], sfr[j][1]));
            mx1 = fmaxf(mx1, fmaxf(sfr[j][2], sfr[j][3]));
        }
        mx0 = fmaxf(mx0, __shfl_xor_sync(0xffffffffu, mx0, 1));
        mx0 = fmaxf(mx0, __shfl_xor_sync(0xffffffffu, mx0, 2));
        mx1 = fmaxf(mx1, __shfl_xor_sync(0xffffffffu, mx1, 1));
        mx1 = fmaxf(mx1, __shfl_xor_sync(0xffffffffu, mx1, 2));
        float mn0 = fmaxf(mrow0, mx0), mn1 = fmaxf(mrow1, mx1);
        float corr0 = __expf(mrow0 - mn0), corr1 = __expf(mrow1 - mn1);

        float sum0 = 0.f, sum1 = 0.f;
        uint32_t ph[2][4], pl[2][4];
#pragma unroll
        for (int kc = 0; kc < 2; kc++) {
            float p00,p01,p02,p03, p10,p11,p12,p13;
            {
                int j = 2*kc;
                p00 = __expf(sfr[j][0] - mn0); p01 = __expf(sfr[j][1] - mn0);
                p02 = __expf(sfr[j][2] - mn1); p03 = __expf(sfr[j][3] - mn1);
                j = 2*kc + 1;
                p10 = __expf(sfr[j][0] - mn0); p11 = __expf(sfr[j][1] - mn0);
                p12 = __expf(sfr[j][2] - mn1); p13 = __expf(sfr[j][3] - mn1);
            }
            sum0 += p00 + p01 + p10 + p11;
            sum1 += p02 + p03 + p12 + p13;
            __nv_bfloat16 h0,l0,h1,l1;
            bsplit(p00,h0,l0); bsplit(p01,h1,l1);
            ph[kc][0] = packb(h0,h1); pl[kc][0] = packb(l0,l1);
            bsplit(p02,h0,l0); bsplit(p03,h1,l1);
            ph[kc][1] = packb(h0,h1); pl[kc][1] = packb(l0,l1);
            bsplit(p10,h0,l0); bsplit(p11,h1,l1);
            ph[kc][2] = packb(h0,h1); pl[kc][2] = packb(l0,l1);
            bsplit(p12,h0,l0); bsplit(p13,h1,l1);
            ph[kc][3] = packb(h0,h1); pl[kc][3] = packb(l0,l1);
        }
        sum0 += __shfl_xor_sync(0xffffffffu, sum0, 1);
        sum0 += __shfl_xor_sync(0xffffffffu, sum0, 2);
        sum1 += __shfl_xor_sync(0xffffffffu, sum1, 1);
        sum1 += __shfl_xor_sync(0xffffffffu, sum1, 2);
        lrow0 = lrow0*corr0 + sum0;
        lrow1 = lrow1*corr1 + sum1;
#pragma unroll
        for (int f = 0; f < 8; f++) {
            yacc[f][0] *= corr0; yacc[f][1] *= corr0;
            yacc[f][2] *= corr1; yacc[f][3] *= corr1;
        }
        mrow0 = mn0; mrow1 = mn1;

#pragma unroll
        for (int f = 0; f < 8; f++) {
            int dr = 8*f + gid;
#pragma unroll
            for (int kc = 0; kc < 2; kc++) {
                uint32_t vbh[2], vbl[2];
                vbh[0] = Vwh[dr*20 + 8*kc + tg];
                vbh[1] = Vwh[dr*20 + 8*kc + tg + 4];
                vbl[0] = Vwl[dr*20 + 8*kc + tg];
                vbl[1] = Vwl[dr*20 + 8*kc + tg + 4];
                mma_bf16(yacc[f], pl[kc], vbh);
                mma_bf16(yacc[f], ph[kc], vbl);
                mma_bf16(yacc[f], ph[kc], vbh);
            }
        }
    }

    float inv0 = 1.f / lrow0, inv1 = 1.f / lrow1;
#pragma unroll
    for (int f = 0; f < 8; f++) {
        int d = hh*kDH + 8*f + 2*tg;
        if (qrow0 < kTA) {
            long a = ((long)(bb*kTA + qrow0))*kC + d;
            __nv_bfloat16 h0,l0,h1,l1;
            bsplit(yacc[f][0]*inv0, h0, l0); bsplit(yacc[f][1]*inv0, h1, l1);
            *(__nv_bfloat162*)&ys[a] = __nv_bfloat162{h0,h1};
            *(__nv_bfloat162*)&ys[planeN + a] = __nv_bfloat162{l0,l1};
        }
        if (qrow1 < kTA) {
            long a = ((long)(bb*kTA + qrow1))*kC + d;
            __nv_bfloat16 h0,l0,h1,l1;
            bsplit(yacc[f][2]*inv1, h0, l0); bsplit(yacc[f][3]*inv1, h1, l1);
            *(__nv_bfloat162*)&ys[a] = __nv_bfloat162{h0,h1};
            *(__nv_bfloat162*)&ys[planeN + a] = __nv_bfloat162{l0,l1};
        }
    }
}

// ---------------- layernorm (full-range variant) ----------------
__global__ __launch_bounds__(256)
void ln_k(const float* __restrict__ x, const float* __restrict__ w,
          const float* __restrict__ b, __nv_bfloat16* __restrict__ o, long planeN)
{
    const long row = blockIdx.x;
    const float* xr = x + row*kC;
    float s = 0.f, s2 = 0.f;
    for (int c = threadIdx.x; c < kC; c += 256) { float v = xr[c]; s += v; s2 += v*v; }
    __shared__ float sh[64];
#pragma unroll
    for (int off=16;off;off>>=1){ s += __shfl_xor_sync(0xffffffffu,s,off); s2 += __shfl_xor_sync(0xffffffffu,s2,off); }
    int wid = threadIdx.x >> 5, lane = threadIdx.x & 31;
    if (lane == 0){ sh[wid] = s; sh[32+wid] = s2; }
    __syncthreads();
    if (threadIdx.x < 32) {
        s  = (lane < 8) ? sh[lane]    : 0.f;
        s2 = (lane < 8) ? sh[32+lane] : 0.f;
#pragma unroll
        for (int off=4;off;off>>=1){ s += __shfl_xor_sync(0xffffffffu,s,off); s2 += __shfl_xor_sync(0xffffffffu,s2,off); }
        if (lane == 0){ sh[0] = s; sh[1] = s2; }
    }
    __syncthreads();
    float mean = sh[0] * (1.f/kC);
    float var  = sh[1] * (1.f/kC) - mean*mean;
    float rstd = rsqrtf(var + 1e-5f);
    for (int c = threadIdx.x; c < kC; c += 256) {
        float v = (xr[c]-mean)*rstd*w[c] + b[c];
        __nv_bfloat16 h,lo2; bsplit(v,h,lo2);
        o[row*kC + c] = h;
        o[planeN + row*kC + c] = lo2;
    }
}

// layernorm over per-batch row range [rowOff, rowOff+rowsPerB)
__global__ __launch_bounds__(256)
void lnr_k(const float* __restrict__ x, const float* __restrict__ w,
           const float* __restrict__ b, __nv_bfloat16* __restrict__ o, long planeN,
           int rowsPerB, int rowOff)
{
    const int bi = blockIdx.x / rowsPerB;
    const int ri = blockIdx.x % rowsPerB;
    const long row = (long)bi*kTA + rowOff + ri;
    const float* xr = x + row*kC;
    float s = 0.f, s2 = 0.f;
    for (int c = threadIdx.x; c < kC; c += 256) { float v = xr[c]; s += v; s2 += v*v; }
    __shared__ float sh[64];
#pragma unroll
    for (int off=16;off;off>>=1){ s += __shfl_xor_sync(0xffffffffu,s,off); s2 += __shfl_xor_sync(0xffffffffu,s2,off); }
    int wid = threadIdx.x >> 5, lane = threadIdx.x & 31;
    if (lane == 0){ sh[wid] = s; sh[32+wid] = s2; }
    __syncthreads();
    if (threadIdx.x < 32) {
        s  = (lane < 8) ? sh[lane]    : 0.f;
        s2 = (lane < 8) ? sh[32+lane] : 0.f;
#pragma unroll
        for (int off=4;off;off>>=1){ s += __shfl_xor_sync(0xffffffffu,s,off); s2 += __shfl_xor_sync(0xffffffffu,s2,off); }
        if (lane == 0){ sh[0] = s; sh[1] = s2; }
    }
    __syncthreads();
    float mean = sh[0] * (1.f/kC);
    float var  = sh[1] * (1.f/kC) - mean*mean;
    float rstd = rsqrtf(var + 1e-5f);
    for (int c = threadIdx.x; c < kC; c += 256) {
        float v = (xr[c]-mean)*rstd*w[c] + b[c];
        __nv_bfloat16 h,lo2; bsplit(v,h,lo2);
        o[row*kC + c] = h;
        o[planeN + row*kC + c] = lo2;
    }
}

// ---------------- small kernels ----------------
__global__ void pool_k(const float* __restrict__ mem, __nv_bfloat16* __restrict__ pooled, long planeN)
{
    const int bm = blockIdx.x;
    const int bI = bm / kM, mI = bm % kM;
    const int seg = kT / kM;
    const float* src = mem + ((long)bI*kT + (long)mI*seg)*kC;
    for (int c = threadIdx.x; c < kC; c += blockDim.x) {
        float s = 0.f;
        for (int t = 0; t < seg; t++) s += src[(long)t*kC + c];
        float v = s * (1.f/seg);
        __nv_bfloat16 h,l; bsplit(v,h,l);
        pooled[(long)bm*kC + c] = h;
        pooled[planeN + (long)bm*kC + c] = l;
    }
}

__global__ void concat_xp_k(const float* __restrict__ pm, const float* __restrict__ x,
                            float* __restrict__ xa)
{
    long i = (long)blockIdx.x*blockDim.x + threadIdx.x;
    constexpr long TOT = (long)kB*(kTA-kM)*kC;
    if (i >= TOT) return;
    int c = (int)(i % kC); long r = i / kC;
    int t = (int)(r % (kTA-kM)); int b = (int)(r / (kTA-kM));
    int ta = t + kM;
    float v = (ta < kPRE) ? pm[(long)(ta-kM)*kC + c]
                          : x[((long)b*kT + (ta-kPRE))*kC + c];
    xa[((long)b*kTA + ta)*kC + c] = v;
}

__global__ void concat_retr_k(const float* __restrict__ retr, float* __restrict__ xa)
{
    long i = (long)blockIdx.x*blockDim.x + threadIdx.x;
    constexpr long TOT = (long)kB*kM*kC;
    if (i >= TOT) return;
    int c = (int)(i % kC); long r = i / kC;
    int t = (int)(r % kM); int b = (int)(r / kM);
    xa[((long)b*kTA + t)*kC + c] = retr[((long)b*kM + t)*kC + c];
}

__global__ void copyout_k(const float* __restrict__ xa2, float* __restrict__ out,
                          __nv_bfloat16* __restrict__ outs, long planeN)
{
    long i = (long)blockIdx.x*blockDim.x + threadIdx.x;
    if (i >= OUT_N) return;
    int c = (int)(i % kC); long r = i / kC; int t = (int)(r % kT); int b = (int)(r / kT);
    float v = xa2[((long)b*kTA + kPRE + t)*kC + c];
    out[i] = v;
    __nv_bfloat16 h,l; bsplit(v,h,l);
    outs[i] = h; outs[planeN + i] = l;
}

__global__ void zero_k(float* __restrict__ a, long n)
{
    long i = (long)blockIdx.x*blockDim.x + threadIdx.x;
    if (i < n) a[i] = 0.f;
}

__global__ void colsum_k(const float* __restrict__ in, float* __restrict__ out,
                         int rows, int cols, int rowsPerSeg)
{
    int z = blockIdx.z;
    in  += (long)z*rows*cols;
    out += (long)z*cols;
    int j = blockIdx.x*blockDim.x + threadIdx.x;
    if (j >= cols) return;
    int t0 = blockIdx.y * rowsPerSeg;
    int t1 = t0 + rowsPerSeg; if (t1 > rows) t1 = rows;
    float s = 0.f;
    for (int t = t0; t < t1; t++) s += in[(long)t*cols + j];
    atomicAdd(out + j, s);
}

__global__ void update_k(const float* __restrict__ w, const float* __restrict__ mom,
                         const float* __restrict__ g, float* __restrict__ outW,
                         float* __restrict__ outM, long n)
{
    long i = (long)blockIdx.x*blockDim.x + threadIdx.x;
    if (i >= n) return;
    float nm = kMU*mom[i] + g[i];
    outM[i] = nm;
    outW[i] = (1.f - kDECAY)*w[i] - kLR*nm;
}

struct SplitJobs {
    const float* src[12];
    __nv_bfloat16* dst[12];
    long off[13];
    int cnt;
};

__global__ void msplit_k(SplitJobs js)
{
    long i = (long)blockIdx.x*blockDim.x + threadIdx.x;
    if (i >= js.off[js.cnt]) return;
    int k = 0;
    while (i >= js.off[k+1]) k++;
    long li = i - js.off[k];
    long n = js.off[k+1] - js.off[k];
    __nv_bfloat16 h,l; bsplit(js.src[k][li], h, l);
    js.dst[k][li] = h;
    js.dst[k][n + li] = l;
}

__global__ void transpose_split_k(const float* __restrict__ in, __nv_bfloat16* __restrict__ out,
                                  long planeN, int rows, int cols)
{
    __shared__ float tile[32][33];
    long zoff = (long)blockIdx.z * rows * cols;
    int c0 = blockIdx.x*32, r0 = blockIdx.y*32;
    int tx = threadIdx.x, ty = threadIdx.y;
#pragma unroll
    for (int i = 0; i < 32; i += 8) {
        int r = r0 + ty + i, c = c0 + tx;
        if (r < rows && c < cols) tile[ty+i][tx] = in[zoff + (long)r*cols + c];
    }
    __syncthreads();
#pragma unroll
    for (int i = 0; i < 32; i += 8) {
        int r = c0 + ty + i, c = r0 + tx;
        if (r < cols && c < rows) {
            __nv_bfloat16 h,l; bsplit(tile[tx][ty+i],h,l);
            out[zoff + (long)r*rows + c] = h;
            out[planeN + zoff + (long)r*rows + c] = l;
        }
    }
}

// ---------------- host side ----------------
template<int EPI, bool WF32, bool WSPLIT>
static void bgemm(cudaStream_t st,
                  const __nv_bfloat16* A, long aPlane, long sA,
                  const __nv_bfloat16* B, long bPlane, long sB,
                  const float* bias, long sBias, const float* res, long sRes,
                  float* C, __nv_bfloat16* Cs, long cPlane, long sC,
                  int M, int N, int K, int batch,
                  float* C2 = nullptr, float scaleP = 0.f)
{
    cudaFuncSetAttribute(bgemm_k<EPI,WF32,WSPLIT>,
                         cudaFuncAttributeMaxDynamicSharedMemorySize, MSMEM);
    dim3 grid(N/MBN, (M + MBM - 1)/MBM, batch);
    bgemm_k<EPI,WF32,WSPLIT><<<grid, 256, MSMEM, st>>>(A, B, bias, res, C, Cs, C2, scaleP,
        M, N, K, aPlane, bPlane, cPlane, sA, sB, sBias, sRes, sC);
}

static inline long cdiv(long a, long b){ return (a + b - 1)/b; }

#define GETF(var, sym) float* var; { void* _p=nullptr; cudaGetSymbolAddress(&_p, sym); var=(float*)_p; }
#define GETB(var, sym) __nv_bfloat16* var; { void* _p=nullptr; cudaGetSymbolAddress(&_p, sym); var=(__nv_bfloat16*)_p; }

extern "C" void kernel_launch(void* const* d_in, const int* in_sizes, int n_in,
                              void* d_out, int out_size)
{
    const float* x       = (const float*)d_in[0];
    const float* persist = (const float*)d_in[1];
    const float* ln1w    = (const float*)d_in[2];
    const float* ln1b    = (const float*)d_in[3];
    const float* ln2w    = (const float*)d_in[4];
    const float* ln2b    = (const float*)d_in[5];
    const float* attnw   = (const float*)d_in[6];
    const float* attnb   = (const float*)d_in[7];
    const float* projw   = (const float*)d_in[8];
    const float* projb   = (const float*)d_in[9];
    const float* fcw     = (const float*)d_in[10];
    const float* fcb     = (const float*)d_in[11];
    const float* mlpw    = (const float*)d_in[12];
    const float* mlpb    = (const float*)d_in[13];
    const float* qw      = (const float*)d_in[14];
    const float* qb      = (const float*)d_in[15];
    const float* kw      = (const float*)d_in[16];
    const float* kb      = (const float*)d_in[17];
    const float* vw      = (const float*)d_in[18];
    const float* vb      = (const float*)d_in[19];
    const float* ow      = (const float*)d_in[20];
    const float* ob      = (const float*)d_in[21];
    const float* memw0   = (const float*)d_in[22];
    const float* memb0   = (const float*)d_in[23];
    const float* memw1   = (const float*)d_in[24];
    const float* memb1   = (const float*)d_in[25];
    const float* momw0   = (const float*)d_in[26];
    const float* momb0   = (const float*)d_in[27];
    const float* momw1   = (const float*)d_in[28];
    const float* momb1   = (const float*)d_in[29];
    float* out = (float*)d_out;

    GETF(zbuf, g_h);    GETF(hh, g_hh);    GETF(memb, g_mem);  GETF(retr, g_retr);
    GETF(xa, g_xa);     GETF(xa2, g_xa2);  GETF(keys, g_keys);
    GETF(vals, g_vals); GETF(dh, g_dh);    GETF(gw0, g_gw0);   GETF(gw1, g_gw1);
    GETF(gb0, g_gb0);   GETF(gb1, g_gb1);

    GETB(px,    s_x);     GETB(pq,    s_q);     GETB(ph,    s_h);     GETB(ppool, s_pool);
    GETB(phln,  s_hln);   GETB(pqkv,  s_qkv);   GETB(py,    s_y);     GETB(phfc,  s_hfc);
    GETB(pout,  s_out);   GETB(pkeys, s_keys);  GETB(phh,   s_hh);    GETB(pdp,   s_dp);
    GETB(pdpT,  s_dpT);   GETB(phhT,  s_hhT);   GETB(pdzT,  s_dzT);   GETB(pkeysT,s_keysT);
    GETB(pw1T,  s_w1T);
    GETB(pqw,   s_qw);    GETB(pkw,   s_kw);    GETB(pvw,   s_vw);    GETB(pow_,  s_ow);
    GETB(pprojw,s_projw); GETB(pattnw,s_attnw); GETB(pfcw,  s_fcw);   GETB(pmlpw, s_mlpw);
    GETB(pw0,   s_w0);    GETB(pw1,   s_w1);

    const long sTC = (long)kT*kC, sTH = (long)kT*kHID;
    const long sW0 = (long)kHID*kC, sW1 = (long)kC*kHID;
    const long sTAC = (long)kTA*kC, sTA3C = (long)kTA*3*kC;
    constexpr int SUF = kTA - kM;   // 1028 suffix rows per batch

    static cudaStream_t s2 = nullptr;
    static cudaEvent_t ev0, ev1, ev2, ev3, ev4, ev5, ev6, ev7;
    if (!s2) {
        cudaStreamCreateWithFlags(&s2, cudaStreamNonBlocking);
        cudaEventCreateWithFlags(&ev0, cudaEventDisableTiming);
        cudaEventCreateWithFlags(&ev1, cudaEventDisableTiming);
        cudaEventCreateWithFlags(&ev2, cudaEventDisableTiming);
        cudaEventCreateWithFlags(&ev3, cudaEventDisableTiming);
        cudaEventCreateWithFlags(&ev4, cudaEventDisableTiming);
        cudaEventCreateWithFlags(&ev5, cudaEventDisableTiming);
        cudaEventCreateWithFlags(&ev6, cudaEventDisableTiming);
        cudaEventCreateWithFlags(&ev7, cudaEventDisableTiming);
    }
    cudaStream_t s0 = 0;

    // ---- batched input splits ----
    {
        SplitJobs js;
        int k = 0; long off = 0;
        auto add = [&](const float* s, __nv_bfloat16* d, long n){
            js.src[k] = s; js.dst[k] = d; js.off[k] = off; off += n; k++;
        };
        add(x,     px,     N_X);
        add(qw,    pqw,    N_SQW);
        add(kw,    pkw,    N_SQW);
        add(vw,    pvw,    N_SQW);
        add(ow,    pow_,   N_SQW);
        add(projw, pprojw, N_SQW);
        add(attnw, pattnw, N_ATTNW);
        add(fcw,   pfcw,   N_FCW);
        add(mlpw,  pmlpw,  N_MLPW);
        add(memw0, pw0,    N_W0);
        add(memw1, pw1,    N_W1);
        js.off[k] = off; js.cnt = k;
        msplit_k<<<(unsigned)cdiv(off,256),256,0,s0>>>(js);
    }
    zero_k<<<(unsigned)cdiv(B0_N,256),256,0,s0>>>(gb0, B0_N);

    // fork: s2 — w1T transpose, suffix concat, suffix ln1, suffix qkv GEMM
    cudaEventRecord(ev0, s0);
    cudaStreamWaitEvent(s2, ev0, 0);
    transpose_split_k<<<dim3(kHID/32, kC/32, kB), dim3(32,8), 0, s2>>>(memw1, pw1T, N_W1T, kC, kHID);
    {
        long n = (long)kB*SUF*kC;
        concat_xp_k<<<(unsigned)cdiv(n,256),256,0,s2>>>(persist, x, xa);
    }
    lnr_k<<<kB*SUF,256,0,s2>>>(xa, ln1w, ln1b, phln, N_HLN, SUF, kM);
    // suffix qkv: batched M=1028, per-batch stride kTA, row offset kM
    bgemm<EP_NONE,false,true>(s2, phln + (long)kM*kC, N_HLN, sTAC,
                              pattnw, N_ATTNW, 0, attnb, 0, nullptr, 0,
                              nullptr, pqkv + (long)kM*3*kC, N_QKV, sTA3C,
                              SUF, 3*kC, kC, kB);
    cudaEventRecord(ev1, s2);

    // ---- forward memory read path (main) ----
    bgemm<EP_NONE,false,true>(s0, px,N_X,0, pqw,N_SQW,0, qb,0, nullptr,0,
                              nullptr, pq,N_Q, 0, kB*kT, kC, kC, 1);
    bgemm<EP_SILU,false,true>(s0, pq,N_Q,sTC, pw0,N_W0,sW0, memb0,kHID, nullptr,0,
                              nullptr, ph,N_H, sTH, kT, kHID, kC, kB);
    bgemm<EP_NONE,true,false>(s0, ph,N_H,sTH, pw1,N_W1,sW1, memb1,kC, nullptr,0,
                              memb, nullptr,0, sTC, kT, kC, kHID, kB);
    pool_k<<<kB*kM, 256, 0, s0>>>(memb, ppool, N_POOL);
    bgemm<EP_NONE,true,false>(s0, ppool,N_POOL,0, pow_,N_SQW,0, ob,0, nullptr,0,
                              retr, nullptr,0, 0, kB*kM, kC, kC, 1);
    {
        long n = (long)kB*kM*kC;
        concat_retr_k<<<(unsigned)cdiv(n,256),256,0,s0>>>(retr, xa);
    }
    // prefix ln1 + qkv (16 rows per batch)
    lnr_k<<<kB*kM,256,0,s0>>>(xa, ln1w, ln1b, phln, N_HLN, kM, 0);
    bgemm<EP_NONE,false,true>(s0, phln, N_HLN, sTAC,
                              pattnw, N_ATTNW, 0, attnb, 0, nullptr, 0,
                              nullptr, pqkv, N_QKV, sTA3C,
                              kM, 3*kC, kC, kB);
    cudaStreamWaitEvent(s0, ev1, 0);   // suffix qkv done

    // ---- transformer block (main) ----
    attn_mma_k<<<dim3((kTA+63)/64, kB*kH), 128, 0, s0>>>(pqkv, N_QKV, py, N_Y);
    bgemm<EP_NONE,true,false>(s0, py,N_Y,0, pprojw,N_SQW,0, projb,0, xa,0,
                              xa2, nullptr,0, 0, kB*kTA, kC, kC, 1);
    ln_k<<<kB*kTA,256,0,s0>>>(xa2, ln2w, ln2b, phln, N_HLN);
    bgemm<EP_GELU,false,true>(s0, phln,N_HLN,0, pfcw,N_FCW,0, fcb,0, nullptr,0,
                              nullptr, phfc,N_HFC, 0, kB*kTA, 4*kC, kC, 1);
    bgemm<EP_NONE,true,false>(s0, phfc,N_HFC,0, pmlpw,N_MLPW,0, mlpb,0, xa2,0,
                              xa2, nullptr,0, 0, kB*kTA, kC, 4*kC, 1);
    copyout_k<<<(unsigned)cdiv(OUT_N,256),256,0,s0>>>(xa2, out, pout, N_OUT);

    // ---- memory write path ----
    cudaEventRecord(ev2, s0);
    cudaStreamWaitEvent(s2, ev2, 0);
    bgemm<EP_NONE,true,false>(s2, pout,N_OUT,0, pvw,N_SQW,0, vb,0, nullptr,0,
                              vals, nullptr,0, 0, kB*kT, kC, kC, 1);
    cudaEventRecord(ev3, s2);

    bgemm<EP_NONE,true,true>(s0, pout,N_OUT,0, pkw,N_SQW,0, kb,0, nullptr,0,
                             keys, pkeys,N_KEYS, 0, kB*kT, kC, kC, 1);
    cudaEventRecord(ev4, s0);
    cudaStreamWaitEvent(s2, ev4, 0);
    transpose_split_k<<<dim3(kC/32, kT/32, kB), dim3(32,8), 0, s2>>>(keys, pkeysT, N_KEYST, kT, kC);
    cudaEventRecord(ev5, s2);

    bgemm<EP_SILUZ,true,true>(s0, pkeys,N_KEYS,sTC, pw0,N_W0,sW0, memb0,kHID, nullptr,0,
                              zbuf, phh,N_HH, sTH, kT, kHID, kC, kB, hh);
    cudaStreamWaitEvent(s0, ev3, 0);
    bgemm<EP_DPRED,true,true>(s0, phh,N_HH,sTH, pw1,N_W1,sW1, memb1,kC, vals,sTC,
                              memb, pdp,N_DP, sTC, kT, kC, kHID, kB,
                              nullptr, 2.f/((float)kT*(float)kC));
    cudaEventRecord(ev6, s0);

    // s2 branch: gb1 + dpT/hhT transposes + gw1 + w1/b1 updates
    cudaStreamWaitEvent(s2, ev6, 0);
    zero_k<<<(unsigned)cdiv(B1_N,256),256,0,s2>>>(gb1, B1_N);
    colsum_k<<<dim3((kC+255)/256, 8, kB),256,0,s2>>>(memb, gb1, kT, kC, kT/8);
    transpose_split_k<<<dim3(kC/32,  kT/32, kB), dim3(32,8), 0, s2>>>(memb, pdpT, N_DPT, kT, kC);
    transpose_split_k<<<dim3(kHID/32,kT/32, kB), dim3(32,8), 0, s2>>>(hh,   phhT, N_HHT, kT, kHID);
    bgemm<EP_NONE,true,false>(s2, pdpT,N_DPT,sTC, phhT,N_HHT,sTH, nullptr,0, nullptr,0,
                              gw1, nullptr,0, sW1, kC, kHID, kT, kB);
    update_k<<<(unsigned)cdiv(W1_N,256),256,0,s2>>>(memw1, momw1, gw1, out+OFF_NW1, out+OFF_NMW1, W1_N);
    update_k<<<(unsigned)cdiv(B1_N,256),256,0,s2>>>(memb1, momb1, gb1, out+OFF_NB1, out+OFF_NMB1, B1_N);
    cudaEventRecord(ev7, s2);

    // main branch: dh + gb0 + dzT + gw0 + w0/b0 updates
    bgemm<EP_DSILU,true,false>(s0, pdp,N_DP,sTC, pw1T,N_W1T,sW0, nullptr,0, zbuf,sTH,
                               dh, nullptr,0, sTH, kT, kHID, kC, kB);
    colsum_k<<<dim3((kHID+255)/256, 8, kB),256,0,s0>>>(dh, gb0, kT, kHID, kT/8);
    update_k<<<(unsigned)cdiv(B0_N,256),256,0,s0>>>(memb0, momb0, gb0, out+OFF_NB0, out+OFF_NMB0, B0_N);
    transpose_split_k<<<dim3(kHID/32,kT/32, kB), dim3(32,8), 0, s0>>>(dh, pdzT, N_DZT, kT, kHID);
    cudaStreamWaitEvent(s0, ev5, 0);
    bgemm<EP_NONE,true,false>(s0, pdzT,N_DZT,sTH, pkeysT,N_KEYST,sTC, nullptr,0, nullptr,0,
                              gw0, nullptr,0, sW0, kHID, kC, kT, kB);
    update_k<<<(unsigned)cdiv(W0_N,256),256,0,s0>>>(memw0, momw0, gw0, out+OFF_NW0, out+OFF_NMW0, W0_N);

    cudaStreamWaitEvent(s0, ev7, 0);

    (void)in_sizes; (void)n_in; (void)out_size;
}